// round 10
// baseline (speedup 1.0000x reference)
#include <cuda_runtime.h>
#include <cuda_bf16.h>
#include <cstdint>

#define BATCH   32
#define CIN     21
#define CH      128
#define LEN     4096
#define NR      8
#define TL      32
#define THREADS 256
#define BPITCH  136      // bf16 per B row; row stride 272B

// ---------------- device scratch ----------------
__device__ float g_bufA[(size_t)BATCH * CH * LEN];
__device__ float g_bufB[(size_t)BATCH * CH * LEN];
// stage1: [layer][sl16: tap,kc,ks][sg2][mg4][half2][mt2][lane32][4] u32
__device__ uint32_t g_w1f[(size_t)NR * 16 * 2 * 4 * 2 * 2 * 32 * 4];
// stage2: [layer][sl8: kc,ks][rk2][mg4][half2][mt2][lane32][4] u32
__device__ uint32_t g_w2f[(size_t)NR * 8 * 2 * 4 * 2 * 2 * 32 * 4];

__device__ __forceinline__ uint32_t sm_u32(const void* p) {
    return (uint32_t)__cvta_generic_to_shared(p);
}
__device__ __forceinline__ void ldm_x4(uint32_t* r, uint32_t addr) {
    asm volatile("ldmatrix.sync.aligned.m8n8.x4.shared.b16 {%0,%1,%2,%3}, [%4];"
                 : "=r"(r[0]), "=r"(r[1]), "=r"(r[2]), "=r"(r[3]) : "r"(addr));
}
__device__ __forceinline__ void mma16816(float* c, const uint32_t* a, const uint32_t* b) {
    asm volatile("mma.sync.aligned.m16n8k16.row.col.f32.bf16.bf16.f32 "
                 "{%0,%1,%2,%3}, {%4,%5,%6,%7}, {%8,%9}, {%0,%1,%2,%3};"
                 : "+f"(c[0]), "+f"(c[1]), "+f"(c[2]), "+f"(c[3])
                 : "r"(a[0]), "r"(a[1]), "r"(a[2]), "r"(a[3]),
                   "r"(b[0]), "r"(b[1]));
}
__device__ __forceinline__ uint4 ldg128(const void* p) {
    uint4 v;
    asm volatile("ld.global.nc.v4.u32 {%0,%1,%2,%3}, [%4];"
                 : "=r"(v.x), "=r"(v.y), "=r"(v.z), "=r"(v.w) : "l"(p));
    return v;
}

// ---------------- weight prep ----------------
__global__ void prep_w1f(const float* __restrict__ sw, const float* __restrict__ gw) {
    int idx = blockIdx.x * blockDim.x + threadIdx.x;
    if (idx >= NR * 16 * 2 * 4 * 2 * 2 * 32 * 4) return;
    int i    = idx & 3;
    int lane = (idx >> 2) & 31;
    int mt   = (idx >> 7) & 1;
    int half = (idx >> 8) & 1;
    int mg   = (idx >> 9) & 3;
    int sg   = (idx >> 11) & 1;
    int sl   = (idx >> 12) & 15;
    int layer = idx >> 16;
    int tap = sl >> 3, kc = (sl >> 1) & 3, ks = sl & 1;
    int row  = mg * 32 + mt * 16 + (lane >> 2) + (i & 1) * 8;
    int kcol = kc * 32 + ks * 16 + (lane & 3) * 2 + ((i >> 1) & 1) * 8;
    const float* src = sg ? gw : sw;
    float v0 = src[(((size_t)layer * CH + row) * CH + kcol) * 2 + tap];
    float v1 = src[(((size_t)layer * CH + row) * CH + kcol + 1) * 2 + tap];
    __nv_bfloat16 b0, b1;
    if (half) {
        b0 = __float2bfloat16(v0 - __bfloat162float(__float2bfloat16(v0)));
        b1 = __float2bfloat16(v1 - __bfloat162float(__float2bfloat16(v1)));
    } else {
        b0 = __float2bfloat16(v0);
        b1 = __float2bfloat16(v1);
    }
    uint32_t pk = ((uint32_t)__bfloat16_as_ushort(b1) << 16) | __bfloat16_as_ushort(b0);
    size_t o = ((((((size_t)layer * 16 + sl) * 2 + sg) * 4 + mg) * 2 + half) * 2 + mt) * 128
             + lane * 4 + i;
    g_w1f[o] = pk;
}

__global__ void prep_w2f(const float* __restrict__ rw, const float* __restrict__ kw) {
    int idx = blockIdx.x * blockDim.x + threadIdx.x;
    if (idx >= NR * 8 * 2 * 4 * 2 * 2 * 32 * 4) return;
    int i    = idx & 3;
    int lane = (idx >> 2) & 31;
    int mt   = (idx >> 7) & 1;
    int half = (idx >> 8) & 1;
    int mg   = (idx >> 9) & 3;
    int rk   = (idx >> 11) & 1;
    int sl   = (idx >> 12) & 7;
    int layer = idx >> 15;
    int kc = sl >> 1, ks = sl & 1;
    int row  = mg * 32 + mt * 16 + (lane >> 2) + (i & 1) * 8;
    int kcol = kc * 32 + ks * 16 + (lane & 3) * 2 + ((i >> 1) & 1) * 8;
    const float* src = rk ? kw : rw;
    float v0 = src[((size_t)layer * CH + row) * CH + kcol];
    float v1 = src[((size_t)layer * CH + row) * CH + kcol + 1];
    __nv_bfloat16 b0, b1;
    if (half) {
        b0 = __float2bfloat16(v0 - __bfloat162float(__float2bfloat16(v0)));
        b1 = __float2bfloat16(v1 - __bfloat162float(__float2bfloat16(v1)));
    } else {
        b0 = __float2bfloat16(v0);
        b1 = __float2bfloat16(v1);
    }
    uint32_t pk = ((uint32_t)__bfloat16_as_ushort(b1) << 16) | __bfloat16_as_ushort(b0);
    size_t o = ((((((size_t)layer * 8 + sl) * 2 + rk) * 4 + mg) * 2 + half) * 2 + mt) * 128
             + lane * 4 + i;
    g_w2f[o] = pk;
}

// ---------------- initial projection ----------------
__global__ void __launch_bounds__(256) proj_kernel(
    const float* __restrict__ x, const float* __restrict__ w0,
    const float* __restrict__ b0, float* __restrict__ h)
{
    __shared__ float xs[CIN][128];
    __shared__ float ws[CH][CIN];
    __shared__ float bs[CH];
    const int b = blockIdx.y, l0 = blockIdx.x * 128, t = threadIdx.x;
    for (int e = t; e < CIN * 128; e += 256) {
        int i = e >> 7, l = e & 127;
        xs[i][l] = x[((size_t)b * CIN + i) * LEN + l0 + l];
    }
    for (int e = t; e < CH * CIN; e += 256) ws[e / CIN][e % CIN] = w0[e];
    if (t < CH) bs[t] = b0[t];
    __syncthreads();
    const int w = t >> 5, lane = t & 31;
    for (int oo = 0; oo < 16; oo++) {
        int o = w * 16 + oo;
        float a0 = bs[o], a1 = bs[o], a2 = bs[o], a3 = bs[o];
        #pragma unroll
        for (int i = 0; i < CIN; i++) {
            float wv = ws[o][i];
            a0 += wv * xs[i][lane];       a1 += wv * xs[i][lane + 32];
            a2 += wv * xs[i][lane + 64];  a3 += wv * xs[i][lane + 96];
        }
        float* dst = h + ((size_t)b * CH + o) * LEN + l0;
        dst[lane] = a0; dst[lane + 32] = a1; dst[lane + 64] = a2; dst[lane + 96] = a3;
    }
}

// ---------------- one WaveNet layer: S/G warp-split, M32xN32 tiles, 3 CTAs/SM ----------------
__global__ void __launch_bounds__(THREADS, 3) layer_reg(
    const float* __restrict__ hin, float* __restrict__ hout,
    float* __restrict__ skipout,
    const uint32_t* __restrict__ w1f, const uint32_t* __restrict__ w2f,
    const float* __restrict__ csw, const float* __restrict__ cgw,
    const float* __restrict__ z, int off2, int first)
{
    __shared__ __align__(16) unsigned char smbuf[4 * TL * BPITCH * 2];
    __nv_bfloat16* b0h = (__nv_bfloat16*)smbuf;                 // [32][136] tap0/g hi
    __nv_bfloat16* b0l = b0h + TL * BPITCH;                     // lo
    __nv_bfloat16* b1h = b0l + TL * BPITCH;                     // tap1 hi
    __nv_bfloat16* b1l = b1h + TL * BPITCH;                     // tap1 lo
    float* Gx = (float*)(smbuf + 2 * TL * BPITCH * 2);          // [128][33] fp32 (reuses b1)

    const int t = threadIdx.x, wid = t >> 5, lane = t & 31;
    const int sg = wid >> 2;              // 0: S/R warps, 1: G/K warps
    const int mg = wid & 3;               // M32 group: rows mg*32..mg*32+31
    const int b = blockIdx.y, l0 = blockIdx.x * TL;

    // ---- fill both tap windows: warp w fills channels w*16..w*16+15, lane = pos ----
    {
        const int p = lane;
        #pragma unroll
        for (int c = 0; c < 16; c++) {
            int ch = wid * 16 + c;
            const float* row = hin + (size_t)(b * CH + ch) * LEN;
            int q0 = l0 + p - off2, q1 = l0 + p - 1;
            float v0 = (q0 >= 0) ? row[q0] : 0.f;
            float v1 = (q1 >= 0) ? row[q1] : 0.f;
            __nv_bfloat16 h0 = __float2bfloat16(v0);
            __nv_bfloat16 h1 = __float2bfloat16(v1);
            b0h[p * BPITCH + ch] = h0;
            b0l[p * BPITCH + ch] = __float2bfloat16(v0 - __bfloat162float(h0));
            b1h[p * BPITCH + ch] = h1;
            b1l[p * BPITCH + ch] = __float2bfloat16(v1 - __bfloat162float(h1));
        }
    }
    __syncthreads();

    float acc[8][4];     // [mt*4+nt][4]
    #pragma unroll
    for (int i = 0; i < 8; i++)
        #pragma unroll
        for (int j = 0; j < 4; j++) acc[i][j] = 0.f;

    const uint32_t b0h_s = sm_u32(b0h), b0l_s = sm_u32(b0l);
    const uint32_t b1h_s = sm_u32(b1h), b1l_s = sm_u32(b1l);
    const int ntx   = (lane >> 4) & 1;
    const int khalf = (lane >> 3) & 1;
    const int brow  = lane & 7;
    const uint32_t r0off = (uint32_t)((ntx * 8 + brow) * (BPITCH * 2)) + (uint32_t)(khalf * 16);
    const uint32_t r1off = r0off + 16u * (BPITCH * 2);

    // ---- stage 1: 16 k-slices; this warp computes only S (sg=0) or only G (sg=1) ----
    const char* wb1 = ((const char*)w1f) + (size_t)(sg * 8192 + mg * 2048) + lane * 16;
    #pragma unroll
    for (int s = 0; s < 16; s++) {
        const int tap = s >> 3, kc = (s >> 1) & 3, ks = s & 1;
        const char* p = wb1 + (size_t)s * 16384;
        uint4 ah0 = ldg128(p);          // hi, M-tile 0
        uint4 ah1 = ldg128(p + 512);    // hi, M-tile 1
        uint4 al0 = ldg128(p + 1024);   // lo, M-tile 0
        uint4 al1 = ldg128(p + 1536);   // lo, M-tile 1
        const uint32_t bh_s = tap ? b1h_s : b0h_s;
        const uint32_t bl_s = tap ? b1l_s : b0l_s;
        const uint32_t kb = (uint32_t)((kc * 32 + ks * 16) * 2);
        uint32_t bh0[4], bl0[4], bh1[4], bl1[4];
        ldm_x4(bh0, bh_s + r0off + kb);
        ldm_x4(bh1, bh_s + r1off + kb);
        ldm_x4(bl0, bl_s + r0off + kb);
        ldm_x4(bl1, bl_s + r1off + kb);
        const uint32_t* Ah0 = (const uint32_t*)&ah0;
        const uint32_t* Ah1 = (const uint32_t*)&ah1;
        const uint32_t* Al0 = (const uint32_t*)&al0;
        const uint32_t* Al1 = (const uint32_t*)&al1;
        // product Ah*Bh
        mma16816(acc[0], Ah0, bh0 + 0);  mma16816(acc[4], Ah1, bh0 + 0);
        mma16816(acc[1], Ah0, bh0 + 2);  mma16816(acc[5], Ah1, bh0 + 2);
        mma16816(acc[2], Ah0, bh1 + 0);  mma16816(acc[6], Ah1, bh1 + 0);
        mma16816(acc[3], Ah0, bh1 + 2);  mma16816(acc[7], Ah1, bh1 + 2);
        // product Ah*Bl
        mma16816(acc[0], Ah0, bl0 + 0);  mma16816(acc[4], Ah1, bl0 + 0);
        mma16816(acc[1], Ah0, bl0 + 2);  mma16816(acc[5], Ah1, bl0 + 2);
        mma16816(acc[2], Ah0, bl1 + 0);  mma16816(acc[6], Ah1, bl1 + 0);
        mma16816(acc[3], Ah0, bl1 + 2);  mma16816(acc[7], Ah1, bl1 + 2);
        // product Al*Bh
        mma16816(acc[0], Al0, bh0 + 0);  mma16816(acc[4], Al1, bh0 + 0);
        mma16816(acc[1], Al0, bh0 + 2);  mma16816(acc[5], Al1, bh0 + 2);
        mma16816(acc[2], Al0, bh1 + 0);  mma16816(acc[6], Al1, bh1 + 0);
        mma16816(acc[3], Al0, bh1 + 2);  mma16816(acc[7], Al1, bh1 + 2);
    }
    __syncthreads();     // windows dead; exchange regions reusable

    const int gid = lane >> 2, tig = lane & 3;

    // ---- G-warps publish G (fp32) into the dead tap1 region ----
    if (sg == 1) {
        #pragma unroll
        for (int a = 0; a < 8; a++) {
            int mt = a >> 2, nt = a & 3;
            #pragma unroll
            for (int j = 0; j < 4; j++) {
                int row = mg * 32 + mt * 16 + gid + ((j >> 1) << 3);
                int col = nt * 8 + tig * 2 + (j & 1);
                Gx[row * 33 + col] = acc[a][j];
            }
        }
    }
    __syncthreads();

    // ---- S-warps: conditioning + gating; g -> window0 (hi/lo) ----
    if (sg == 0) {
        const float* zrow = z + (size_t)b * LEN + l0;
        #pragma unroll
        for (int a = 0; a < 8; a++) {
            int mt = a >> 2, nt = a & 3;
            #pragma unroll
            for (int j = 0; j < 4; j++) {
                int row = mg * 32 + mt * 16 + gid + ((j >> 1) << 3);
                int col = nt * 8 + tig * 2 + (j & 1);
                float zl = zrow[col];
                float s  = acc[a][j] + csw[row] * zl;
                float gt = Gx[row * 33 + col] + cgw[row] * zl;
                float gval = s * (1.f / (1.f + __expf(-gt)));
                __nv_bfloat16 hi = __float2bfloat16(gval);
                b0h[col * BPITCH + row] = hi;
                b0l[col * BPITCH + row] = __float2bfloat16(gval - __bfloat162float(hi));
            }
        }
    }
    #pragma unroll
    for (int i = 0; i < 8; i++)
        #pragma unroll
        for (int j = 0; j < 4; j++) acc[i][j] = 0.f;
    __syncthreads();

    // ---- stage 2: R (sg=0) / K (sg=1) over g-window ----
    const char* wb2 = ((const char*)w2f) + (size_t)(sg * 8192 + mg * 2048) + lane * 16;
    #pragma unroll
    for (int s = 0; s < 8; s++) {
        const int kc = s >> 1, ks = s & 1;
        const char* p = wb2 + (size_t)s * 16384;
        uint4 ah0 = ldg128(p);
        uint4 ah1 = ldg128(p + 512);
        uint4 al0 = ldg128(p + 1024);
        uint4 al1 = ldg128(p + 1536);
        const uint32_t kb = (uint32_t)((kc * 32 + ks * 16) * 2);
        uint32_t bh0[4], bl0[4], bh1[4], bl1[4];
        ldm_x4(bh0, b0h_s + r0off + kb);
        ldm_x4(bh1, b0h_s + r1off + kb);
        ldm_x4(bl0, b0l_s + r0off + kb);
        ldm_x4(bl1, b0l_s + r1off + kb);
        const uint32_t* Ah0 = (const uint32_t*)&ah0;
        const uint32_t* Ah1 = (const uint32_t*)&ah1;
        const uint32_t* Al0 = (const uint32_t*)&al0;
        const uint32_t* Al1 = (const uint32_t*)&al1;
        mma16816(acc[0], Ah0, bh0 + 0);  mma16816(acc[4], Ah1, bh0 + 0);
        mma16816(acc[1], Ah0, bh0 + 2);  mma16816(acc[5], Ah1, bh0 + 2);
        mma16816(acc[2], Ah0, bh1 + 0);  mma16816(acc[6], Ah1, bh1 + 0);
        mma16816(acc[3], Ah0, bh1 + 2);  mma16816(acc[7], Ah1, bh1 + 2);
        mma16816(acc[0], Ah0, bl0 + 0);  mma16816(acc[4], Ah1, bl0 + 0);
        mma16816(acc[1], Ah0, bl0 + 2);  mma16816(acc[5], Ah1, bl0 + 2);
        mma16816(acc[2], Ah0, bl1 + 0);  mma16816(acc[6], Ah1, bl1 + 0);
        mma16816(acc[3], Ah0, bl1 + 2);  mma16816(acc[7], Ah1, bl1 + 2);
        mma16816(acc[0], Al0, bh0 + 0);  mma16816(acc[4], Al1, bh0 + 0);
        mma16816(acc[1], Al0, bh0 + 2);  mma16816(acc[5], Al1, bh0 + 2);
        mma16816(acc[2], Al0, bh1 + 0);  mma16816(acc[6], Al1, bh1 + 0);
        mma16816(acc[3], Al0, bh1 + 2);  mma16816(acc[7], Al1, bh1 + 2);
    }

    // ---- epilogue: sg=0 writes h (= g + res, or hin + res on layer 0); sg=1 writes skip ----
    #pragma unroll
    for (int a = 0; a < 8; a++) {
        int mt = a >> 2, nt = a & 3;
        #pragma unroll
        for (int j = 0; j < 4; j++) {
            int row = mg * 32 + mt * 16 + gid + ((j >> 1) << 3);
            int col = nt * 8 + tig * 2 + (j & 1);
            size_t idx = (size_t)(b * CH + row) * LEN + l0 + col;
            if (sg == 0) {
                float res = acc[a][j];
                float hv;
                if (first) {
                    hv = hin[idx] + res;
                } else {
                    float g = __bfloat162float(b0h[col * BPITCH + row]) +
                              __bfloat162float(b0l[col * BPITCH + row]);
                    hv = g + res;
                }
                hout[idx] = hv;
            } else {
                float sk = acc[a][j];
                if (first) skipout[idx] = sk;
                else       skipout[idx] += sk;
            }
        }
    }
}

extern "C" void kernel_launch(void* const* d_in, const int* in_sizes, int n_in,
                              void* d_out, int out_size) {
    (void)in_sizes; (void)n_in; (void)out_size;
    const float* x   = (const float*)d_in[0];
    const float* z   = (const float*)d_in[1];
    const float* w0  = (const float*)d_in[2];
    const float* b0  = (const float*)d_in[3];
    const float* sw  = (const float*)d_in[4];
    const float* gw  = (const float*)d_in[5];
    const float* csw = (const float*)d_in[6];
    const float* cgw = (const float*)d_in[7];
    const float* rw  = (const float*)d_in[8];
    const float* kw  = (const float*)d_in[9];

    float* outH = (float*)d_out;
    float* outS = outH + (size_t)BATCH * CH * LEN;

    float *bufA, *bufB;
    cudaGetSymbolAddress((void**)&bufA, g_bufA);
    cudaGetSymbolAddress((void**)&bufB, g_bufB);
    uint32_t *w1p, *w2p;
    cudaGetSymbolAddress((void**)&w1p, g_w1f);
    cudaGetSymbolAddress((void**)&w2p, g_w2f);

    prep_w1f<<<2048, 256>>>(sw, gw);
    prep_w2f<<<1024, 256>>>(rw, kw);
    proj_kernel<<<dim3(LEN / 128, BATCH), 256>>>(x, w0, b0, bufA);

    const float* cur = bufA;
    for (int ii = 0; ii < NR; ii++) {
        int d    = 1 << ii;
        int off2 = (ii == 0) ? 2 : d + 1;
        float* nxt = (ii == NR - 1) ? outH : ((cur == bufA) ? bufB : bufA);
        layer_reg<<<dim3(LEN / TL, BATCH), THREADS>>>(
            cur, nxt, outS,
            w1p + (size_t)ii * 16 * 2 * 4 * 2 * 2 * 32 * 4,
            w2p + (size_t)ii * 8 * 2 * 4 * 2 * 2 * 32 * 4,
            csw + ii * CH, cgw + ii * CH,
            z, off2, ii == 0 ? 1 : 0);
        cur = nxt;
    }
}

// round 11
// speedup vs baseline: 1.0189x; 1.0189x over previous
#include <cuda_runtime.h>
#include <cuda_bf16.h>
#include <cstdint>

#define BATCH   32
#define CIN     21
#define CH      128
#define LEN     4096
#define NR      8
#define TL      32
#define THREADS 256
#define BPITCH  136      // bf16 per B row; row stride 272B (conflict-free)

// ---------------- device scratch ----------------
__device__ float g_bufA[(size_t)BATCH * CH * LEN];
__device__ float g_bufB[(size_t)BATCH * CH * LEN];
// fragment-major stage1 weights: [layer][slice16: tap,kc,ks][mat4: Sh,Sl,Gh,Gl][mg8][lane32] x uint4
__device__ uint32_t g_w1f[(size_t)NR * 16 * 4 * 8 * 32 * 4];
// stage2: [layer][slice8: kc,ks][mat4: Rh,Rl,Kh,Kl][mg8][lane32] x uint4
__device__ uint32_t g_w2f[(size_t)NR * 8 * 4 * 8 * 32 * 4];

__device__ __forceinline__ uint32_t sm_u32(const void* p) {
    return (uint32_t)__cvta_generic_to_shared(p);
}
__device__ __forceinline__ void ldm_x4(uint32_t* r, uint32_t addr) {
    asm volatile("ldmatrix.sync.aligned.m8n8.x4.shared.b16 {%0,%1,%2,%3}, [%4];"
                 : "=r"(r[0]), "=r"(r[1]), "=r"(r[2]), "=r"(r[3]) : "r"(addr));
}
__device__ __forceinline__ void mma16816(float* c, const uint32_t* a, const uint32_t* b) {
    asm volatile("mma.sync.aligned.m16n8k16.row.col.f32.bf16.bf16.f32 "
                 "{%0,%1,%2,%3}, {%4,%5,%6,%7}, {%8,%9}, {%0,%1,%2,%3};"
                 : "+f"(c[0]), "+f"(c[1]), "+f"(c[2]), "+f"(c[3])
                 : "r"(a[0]), "r"(a[1]), "r"(a[2]), "r"(a[3]),
                   "r"(b[0]), "r"(b[1]));
}
__device__ __forceinline__ uint4 ldg128(const void* p) {
    uint4 v;
    asm volatile("ld.global.nc.v4.u32 {%0,%1,%2,%3}, [%4];"
                 : "=r"(v.x), "=r"(v.y), "=r"(v.z), "=r"(v.w) : "l"(p));
    return v;
}

// ---------------- weight prep: fragment-major, bf16 hi/lo split ----------------
__global__ void prep_w1f(const float* __restrict__ sw, const float* __restrict__ gw) {
    int idx = blockIdx.x * blockDim.x + threadIdx.x;
    if (idx >= NR * 16 * 4 * 8 * 32 * 4) return;
    int i    = idx & 3;
    int lane = (idx >> 2) & 31;
    int mgi  = (idx >> 7) & 7;
    int mat  = (idx >> 10) & 3;
    int sl   = (idx >> 12) & 15;
    int layer = idx >> 16;
    int tap = sl >> 3, kc = (sl >> 1) & 3, ks = sl & 1;
    int row  = mgi * 16 + (lane >> 2) + (i & 1) * 8;
    int kcol = kc * 32 + ks * 16 + (lane & 3) * 2 + ((i >> 1) & 1) * 8;
    const float* src = (mat >> 1) ? gw : sw;
    int half = mat & 1;
    float v0 = src[(((size_t)layer * CH + row) * CH + kcol) * 2 + tap];
    float v1 = src[(((size_t)layer * CH + row) * CH + kcol + 1) * 2 + tap];
    __nv_bfloat16 b0, b1;
    if (half) {
        b0 = __float2bfloat16(v0 - __bfloat162float(__float2bfloat16(v0)));
        b1 = __float2bfloat16(v1 - __bfloat162float(__float2bfloat16(v1)));
    } else {
        b0 = __float2bfloat16(v0);
        b1 = __float2bfloat16(v1);
    }
    uint32_t pk = ((uint32_t)__bfloat16_as_ushort(b1) << 16) | __bfloat16_as_ushort(b0);
    size_t o = ((((size_t)layer * 16 + sl) * 4 + mat) * 8 + mgi) * 32 + lane;
    g_w1f[o * 4 + i] = pk;
}

__global__ void prep_w2f(const float* __restrict__ rw, const float* __restrict__ kw) {
    int idx = blockIdx.x * blockDim.x + threadIdx.x;
    if (idx >= NR * 8 * 4 * 8 * 32 * 4) return;
    int i    = idx & 3;
    int lane = (idx >> 2) & 31;
    int mgi  = (idx >> 7) & 7;
    int mat  = (idx >> 10) & 3;
    int sl   = (idx >> 12) & 7;
    int layer = idx >> 15;
    int kc = sl >> 1, ks = sl & 1;
    int row  = mgi * 16 + (lane >> 2) + (i & 1) * 8;
    int kcol = kc * 32 + ks * 16 + (lane & 3) * 2 + ((i >> 1) & 1) * 8;
    const float* src = (mat >> 1) ? kw : rw;
    int half = mat & 1;
    float v0 = src[((size_t)layer * CH + row) * CH + kcol];
    float v1 = src[((size_t)layer * CH + row) * CH + kcol + 1];
    __nv_bfloat16 b0, b1;
    if (half) {
        b0 = __float2bfloat16(v0 - __bfloat162float(__float2bfloat16(v0)));
        b1 = __float2bfloat16(v1 - __bfloat162float(__float2bfloat16(v1)));
    } else {
        b0 = __float2bfloat16(v0);
        b1 = __float2bfloat16(v1);
    }
    uint32_t pk = ((uint32_t)__bfloat16_as_ushort(b1) << 16) | __bfloat16_as_ushort(b0);
    size_t o = ((((size_t)layer * 8 + sl) * 4 + mat) * 8 + mgi) * 32 + lane;
    g_w2f[o * 4 + i] = pk;
}

// ---------------- initial projection ----------------
__global__ void __launch_bounds__(256) proj_kernel(
    const float* __restrict__ x, const float* __restrict__ w0,
    const float* __restrict__ b0, float* __restrict__ h)
{
    __shared__ float xs[CIN][128];
    __shared__ float ws[CH][CIN];
    __shared__ float bs[CH];
    const int b = blockIdx.y, l0 = blockIdx.x * 128, t = threadIdx.x;
    for (int e = t; e < CIN * 128; e += 256) {
        int i = e >> 7, l = e & 127;
        xs[i][l] = x[((size_t)b * CIN + i) * LEN + l0 + l];
    }
    for (int e = t; e < CH * CIN; e += 256) ws[e / CIN][e % CIN] = w0[e];
    if (t < CH) bs[t] = b0[t];
    __syncthreads();
    const int w = t >> 5, lane = t & 31;
    for (int oo = 0; oo < 16; oo++) {
        int o = w * 16 + oo;
        float a0 = bs[o], a1 = bs[o], a2 = bs[o], a3 = bs[o];
        #pragma unroll
        for (int i = 0; i < CIN; i++) {
            float wv = ws[o][i];
            a0 += wv * xs[i][lane];       a1 += wv * xs[i][lane + 32];
            a2 += wv * xs[i][lane + 64];  a3 += wv * xs[i][lane + 96];
        }
        float* dst = h + ((size_t)b * CH + o) * LEN + l0;
        dst[lane] = a0; dst[lane + 32] = a1; dst[lane + 64] = a2; dst[lane + 96] = a3;
    }
}

// ---------------- one WaveNet layer: TL=32, M16xN32 warps, 3 CTAs/SM ----------------
// merged=1: single window of span=TL+off2 rows (tap1 base = hi + (off2-1) rows)
// merged=0: dual 32-row windows (tap1 base = hi + 32 rows)
__global__ void __launch_bounds__(THREADS, 3) layer_reg(
    const float* __restrict__ hin, float* __restrict__ hout,
    float* __restrict__ skipout,
    const uint4* __restrict__ w1f, const uint4* __restrict__ w2f,
    const float* __restrict__ csw, const float* __restrict__ cgw,
    const float* __restrict__ z, int off2, int first, int merged)
{
    extern __shared__ __align__(16) unsigned char smraw[];
    __nv_bfloat16* whi = (__nv_bfloat16*)smraw;
    const int spanRows = merged ? (TL + off2) : 2 * TL;
    __nv_bfloat16* wlo = whi + spanRows * BPITCH;

    const int t = threadIdx.x, wid = t >> 5, lane = t & 31;
    const int mg = wid;                                    // 8 M-group warps
    const int b = blockIdx.y, l0 = blockIdx.x * TL;

    // ---- fill window(s): warp w handles channels w*16..w*16+15, lanes over positions ----
    if (merged) {
        #pragma unroll
        for (int c = 0; c < 16; c++) {
            int ch = wid * 16 + c;
            const float* row = hin + (size_t)(b * CH + ch) * LEN;
            for (int p = lane; p < spanRows; p += 32) {
                int q = l0 + p - off2;
                float v = (q >= 0) ? row[q] : 0.f;
                __nv_bfloat16 h = __float2bfloat16(v);
                whi[p * BPITCH + ch] = h;
                wlo[p * BPITCH + ch] = __float2bfloat16(v - __bfloat162float(h));
            }
        }
    } else {
        const int p = lane;
        #pragma unroll
        for (int c = 0; c < 16; c++) {
            int ch = wid * 16 + c;
            const float* row = hin + (size_t)(b * CH + ch) * LEN;
            int q0 = l0 + p - off2, q1 = l0 + p - 1;
            float v0 = (q0 >= 0) ? row[q0] : 0.f;
            float v1 = (q1 >= 0) ? row[q1] : 0.f;
            __nv_bfloat16 h0 = __float2bfloat16(v0);
            __nv_bfloat16 h1 = __float2bfloat16(v1);
            whi[p * BPITCH + ch] = h0;
            wlo[p * BPITCH + ch] = __float2bfloat16(v0 - __bfloat162float(h0));
            whi[(TL + p) * BPITCH + ch] = h1;
            wlo[(TL + p) * BPITCH + ch] = __float2bfloat16(v1 - __bfloat162float(h1));
        }
    }
    __syncthreads();

    float accS[4][4], accG[4][4];
    #pragma unroll
    for (int i = 0; i < 4; i++)
        #pragma unroll
        for (int j = 0; j < 4; j++) { accS[i][j] = 0.f; accG[i][j] = 0.f; }

    const uint32_t b0h_s = sm_u32(whi), b0l_s = sm_u32(wlo);
    const uint32_t t1B = (uint32_t)((merged ? (off2 - 1) : TL) * (BPITCH * 2));
    const uint32_t b1h_s = b0h_s + t1B, b1l_s = b0l_s + t1B;
    const int ntx   = (lane >> 4) & 1;
    const int khalf = (lane >> 3) & 1;
    const int brow  = lane & 7;
    const uint32_t r0off = (uint32_t)((ntx * 8 + brow) * (BPITCH * 2)) + (uint32_t)(khalf * 16);
    const uint32_t r1off = r0off + 16u * (BPITCH * 2);

    // ---- stage 1: 16 k-slices (tap x kc x ks), A direct from global ----
    const char* wb1 = (const char*)(w1f + (size_t)mg * 32 + lane);
    #pragma unroll
    for (int s = 0; s < 16; s++) {
        const int tap = s >> 3, kc = (s >> 1) & 3, ks = s & 1;
        uint4 aSh = ldg128(wb1 + (size_t)(s * 4 + 0) * 4096);
        uint4 aSl = ldg128(wb1 + (size_t)(s * 4 + 1) * 4096);
        uint4 aGh = ldg128(wb1 + (size_t)(s * 4 + 2) * 4096);
        uint4 aGl = ldg128(wb1 + (size_t)(s * 4 + 3) * 4096);
        const uint32_t bh_s = tap ? b1h_s : b0h_s;
        const uint32_t bl_s = tap ? b1l_s : b0l_s;
        const uint32_t kb = (uint32_t)((kc * 32 + ks * 16) * 2);
        uint32_t bh0[4], bl0[4], bh1[4], bl1[4];
        ldm_x4(bh0, bh_s + r0off + kb);
        ldm_x4(bl0, bl_s + r0off + kb);
        ldm_x4(bh1, bh_s + r1off + kb);
        ldm_x4(bl1, bl_s + r1off + kb);
        #pragma unroll
        for (int hnt = 0; hnt < 2; hnt++) {
            mma16816(accS[hnt], (const uint32_t*)&aSh, bh0 + 2 * hnt);
            mma16816(accG[hnt], (const uint32_t*)&aGh, bh0 + 2 * hnt);
            mma16816(accS[hnt], (const uint32_t*)&aSh, bl0 + 2 * hnt);
            mma16816(accG[hnt], (const uint32_t*)&aGh, bl0 + 2 * hnt);
            mma16816(accS[hnt], (const uint32_t*)&aSl, bh0 + 2 * hnt);
            mma16816(accG[hnt], (const uint32_t*)&aGl, bh0 + 2 * hnt);
        }
        #pragma unroll
        for (int hnt = 0; hnt < 2; hnt++) {
            mma16816(accS[2 + hnt], (const uint32_t*)&aSh, bh1 + 2 * hnt);
            mma16816(accG[2 + hnt], (const uint32_t*)&aGh, bh1 + 2 * hnt);
            mma16816(accS[2 + hnt], (const uint32_t*)&aSh, bl1 + 2 * hnt);
            mma16816(accG[2 + hnt], (const uint32_t*)&aGh, bl1 + 2 * hnt);
            mma16816(accS[2 + hnt], (const uint32_t*)&aSl, bh1 + 2 * hnt);
            mma16816(accG[2 + hnt], (const uint32_t*)&aGl, bh1 + 2 * hnt);
        }
    }

    // ---- conditioning + gating; g -> rows 0..31 of hi/lo window ----
    const int gid = lane >> 2, tig = lane & 3;
    const int ch0 = mg * 16 + gid;
    {
        float cs0 = csw[ch0], cs1 = csw[ch0 + 8];
        float cg0 = cgw[ch0], cg1 = cgw[ch0 + 8];
        const float* zrow = z + (size_t)b * LEN + l0;
        float gv[4][4];
        #pragma unroll
        for (int nt = 0; nt < 4; nt++) {
            int n0 = nt * 8 + tig * 2;
            float z0 = zrow[n0], z1 = zrow[n0 + 1];
            float s0v = accS[nt][0] + cs0 * z0, g0v = accG[nt][0] + cg0 * z0;
            float s1v = accS[nt][1] + cs0 * z1, g1v = accG[nt][1] + cg0 * z1;
            float s2v = accS[nt][2] + cs1 * z0, g2v = accG[nt][2] + cg1 * z0;
            float s3v = accS[nt][3] + cs1 * z1, g3v = accG[nt][3] + cg1 * z1;
            gv[nt][0] = s0v / (1.f + __expf(-g0v));
            gv[nt][1] = s1v / (1.f + __expf(-g1v));
            gv[nt][2] = s2v / (1.f + __expf(-g2v));
            gv[nt][3] = s3v / (1.f + __expf(-g3v));
        }
        __syncthreads();   // all stage-1 window reads complete before overwrite
        #pragma unroll
        for (int nt = 0; nt < 4; nt++) {
            int n0 = nt * 8 + tig * 2;
            #pragma unroll
            for (int j = 0; j < 4; j++) {
                int n  = n0 + (j & 1);
                int ch = ch0 + ((j >> 1) << 3);
                __nv_bfloat16 hi = __float2bfloat16(gv[nt][j]);
                whi[n * BPITCH + ch] = hi;
                wlo[n * BPITCH + ch] = __float2bfloat16(gv[nt][j] - __bfloat162float(hi));
            }
        }
    }
    #pragma unroll
    for (int i = 0; i < 4; i++)
        #pragma unroll
        for (int j = 0; j < 4; j++) { accS[i][j] = 0.f; accG[i][j] = 0.f; }
    __syncthreads();

    // ---- stage 2: res/skip over g (rows 0..31 of window) ----
    const char* wb2 = (const char*)(w2f + (size_t)mg * 32 + lane);
    #pragma unroll
    for (int s = 0; s < 8; s++) {
        const int kc = s >> 1, ks = s & 1;
        uint4 aRh = ldg128(wb2 + (size_t)(s * 4 + 0) * 4096);
        uint4 aRl = ldg128(wb2 + (size_t)(s * 4 + 1) * 4096);
        uint4 aKh = ldg128(wb2 + (size_t)(s * 4 + 2) * 4096);
        uint4 aKl = ldg128(wb2 + (size_t)(s * 4 + 3) * 4096);
        const uint32_t kb = (uint32_t)((kc * 32 + ks * 16) * 2);
        uint32_t bh0[4], bl0[4], bh1[4], bl1[4];
        ldm_x4(bh0, b0h_s + r0off + kb);
        ldm_x4(bl0, b0l_s + r0off + kb);
        ldm_x4(bh1, b0h_s + r1off + kb);
        ldm_x4(bl1, b0l_s + r1off + kb);
        #pragma unroll
        for (int hnt = 0; hnt < 2; hnt++) {
            mma16816(accS[hnt], (const uint32_t*)&aRh, bh0 + 2 * hnt);
            mma16816(accG[hnt], (const uint32_t*)&aKh, bh0 + 2 * hnt);
            mma16816(accS[hnt], (const uint32_t*)&aRh, bl0 + 2 * hnt);
            mma16816(accG[hnt], (const uint32_t*)&aKh, bl0 + 2 * hnt);
            mma16816(accS[hnt], (const uint32_t*)&aRl, bh0 + 2 * hnt);
            mma16816(accG[hnt], (const uint32_t*)&aKl, bh0 + 2 * hnt);
        }
        #pragma unroll
        for (int hnt = 0; hnt < 2; hnt++) {
            mma16816(accS[2 + hnt], (const uint32_t*)&aRh, bh1 + 2 * hnt);
            mma16816(accG[2 + hnt], (const uint32_t*)&aKh, bh1 + 2 * hnt);
            mma16816(accS[2 + hnt], (const uint32_t*)&aRh, bl1 + 2 * hnt);
            mma16816(accG[2 + hnt], (const uint32_t*)&aKh, bl1 + 2 * hnt);
            mma16816(accS[2 + hnt], (const uint32_t*)&aRl, bh1 + 2 * hnt);
            mma16816(accG[2 + hnt], (const uint32_t*)&aKl, bh1 + 2 * hnt);
        }
    }

    // ---- epilogue ----
    #pragma unroll
    for (int nt = 0; nt < 4; nt++) {
        int n0 = nt * 8 + tig * 2;
        #pragma unroll
        for (int j = 0; j < 4; j++) {
            int n  = n0 + (j & 1);
            int ch = ch0 + ((j >> 1) << 3);
            size_t idx = (size_t)(b * CH + ch) * LEN + l0 + n;
            float res = accS[nt][j], sk = accG[nt][j];
            float hv;
            if (first) {
                hv = hin[idx] + res;
            } else {
                float g = __bfloat162float(whi[n * BPITCH + ch]) +
                          __bfloat162float(wlo[n * BPITCH + ch]);
                hv = g + res;
            }
            hout[idx] = hv;
            if (first) skipout[idx] = sk;
            else       skipout[idx] += sk;
        }
    }
}

extern "C" void kernel_launch(void* const* d_in, const int* in_sizes, int n_in,
                              void* d_out, int out_size) {
    (void)in_sizes; (void)n_in; (void)out_size;
    const float* x   = (const float*)d_in[0];
    const float* z   = (const float*)d_in[1];
    const float* w0  = (const float*)d_in[2];
    const float* b0  = (const float*)d_in[3];
    const float* sw  = (const float*)d_in[4];
    const float* gw  = (const float*)d_in[5];
    const float* csw = (const float*)d_in[6];
    const float* cgw = (const float*)d_in[7];
    const float* rw  = (const float*)d_in[8];
    const float* kw  = (const float*)d_in[9];

    float* outH = (float*)d_out;
    float* outS = outH + (size_t)BATCH * CH * LEN;

    float *bufA, *bufB;
    cudaGetSymbolAddress((void**)&bufA, g_bufA);
    cudaGetSymbolAddress((void**)&bufB, g_bufB);
    uint32_t *w1p, *w2p;
    cudaGetSymbolAddress((void**)&w1p, g_w1f);
    cudaGetSymbolAddress((void**)&w2p, g_w2f);

    // max dynamic smem: merged layer 5 (span 65): 2*65*272 = 35360 B
    cudaFuncSetAttribute(layer_reg,
                         cudaFuncAttributeMaxDynamicSharedMemorySize, 35360);

    prep_w1f<<<2048, 256>>>(sw, gw);
    prep_w2f<<<1024, 256>>>(rw, kw);
    proj_kernel<<<dim3(LEN / 128, BATCH), 256>>>(x, w0, b0, bufA);

    const float* cur = bufA;
    for (int ii = 0; ii < NR; ii++) {
        int d    = 1 << ii;
        int off2 = (ii == 0) ? 2 : d + 1;
        int merged = (ii <= 5) ? 1 : 0;   // span = TL+off2 <= 65 rows
        int smem = merged ? 2 * (TL + off2) * BPITCH * 2
                          : 4 * TL * BPITCH * 2;
        float* nxt = (ii == NR - 1) ? outH : ((cur == bufA) ? bufB : bufA);
        layer_reg<<<dim3(LEN / TL, BATCH), THREADS, smem>>>(
            cur, nxt, outS,
            (const uint4*)(w1p + (size_t)ii * 16 * 4 * 8 * 32 * 4),
            (const uint4*)(w2p + (size_t)ii * 8 * 4 * 8 * 32 * 4),
            csw + ii * CH, cgw + ii * CH,
            z, off2, ii == 0 ? 1 : 0, merged);
        cur = nxt;
    }
}

// round 12
// speedup vs baseline: 1.0376x; 1.0184x over previous
#include <cuda_runtime.h>
#include <cuda_bf16.h>
#include <cstdint>

#define BATCH   32
#define CIN     21
#define CH      128
#define LEN     4096
#define NR      8
#define TL      32
#define THREADS 256
#define BPITCH  136      // bf16 per B row; row stride 272B (conflict-free)

// ---------------- device scratch ----------------
__device__ float g_bufA[(size_t)BATCH * CH * LEN];
__device__ float g_bufB[(size_t)BATCH * CH * LEN];
// fragment-major stage1 weights: [layer][slice16: tap,kc,ks][mat4: Sh,Sl,Gh,Gl][mg8][lane32] x uint4
__device__ uint32_t g_w1f[(size_t)NR * 16 * 4 * 8 * 32 * 4];
// stage2: [layer][slice8: kc,ks][mat4: Rh,Rl,Kh,Kl][mg8][lane32] x uint4
__device__ uint32_t g_w2f[(size_t)NR * 8 * 4 * 8 * 32 * 4];

__device__ __forceinline__ uint32_t sm_u32(const void* p) {
    return (uint32_t)__cvta_generic_to_shared(p);
}
__device__ __forceinline__ void ldm_x4(uint32_t* r, uint32_t addr) {
    asm volatile("ldmatrix.sync.aligned.m8n8.x4.shared.b16 {%0,%1,%2,%3}, [%4];"
                 : "=r"(r[0]), "=r"(r[1]), "=r"(r[2]), "=r"(r[3]) : "r"(addr));
}
__device__ __forceinline__ void mma16816(float* c, const uint32_t* a, const uint32_t* b) {
    asm volatile("mma.sync.aligned.m16n8k16.row.col.f32.bf16.bf16.f32 "
                 "{%0,%1,%2,%3}, {%4,%5,%6,%7}, {%8,%9}, {%0,%1,%2,%3};"
                 : "+f"(c[0]), "+f"(c[1]), "+f"(c[2]), "+f"(c[3])
                 : "r"(a[0]), "r"(a[1]), "r"(a[2]), "r"(a[3]),
                   "r"(b[0]), "r"(b[1]));
}
__device__ __forceinline__ uint4 ldg128(const void* p) {
    uint4 v;
    asm volatile("ld.global.nc.v4.u32 {%0,%1,%2,%3}, [%4];"
                 : "=r"(v.x), "=r"(v.y), "=r"(v.z), "=r"(v.w) : "l"(p));
    return v;
}

// ---------------- weight prep: fragment-major, bf16 hi/lo split ----------------
__global__ void prep_w1f(const float* __restrict__ sw, const float* __restrict__ gw) {
    int idx = blockIdx.x * blockDim.x + threadIdx.x;
    if (idx >= NR * 16 * 4 * 8 * 32 * 4) return;
    int i    = idx & 3;
    int lane = (idx >> 2) & 31;
    int mgi  = (idx >> 7) & 7;
    int mat  = (idx >> 10) & 3;
    int sl   = (idx >> 12) & 15;
    int layer = idx >> 16;
    int tap = sl >> 3, kc = (sl >> 1) & 3, ks = sl & 1;
    int row  = mgi * 16 + (lane >> 2) + (i & 1) * 8;
    int kcol = kc * 32 + ks * 16 + (lane & 3) * 2 + ((i >> 1) & 1) * 8;
    const float* src = (mat >> 1) ? gw : sw;
    int half = mat & 1;
    float v0 = src[(((size_t)layer * CH + row) * CH + kcol) * 2 + tap];
    float v1 = src[(((size_t)layer * CH + row) * CH + kcol + 1) * 2 + tap];
    __nv_bfloat16 b0, b1;
    if (half) {
        b0 = __float2bfloat16(v0 - __bfloat162float(__float2bfloat16(v0)));
        b1 = __float2bfloat16(v1 - __bfloat162float(__float2bfloat16(v1)));
    } else {
        b0 = __float2bfloat16(v0);
        b1 = __float2bfloat16(v1);
    }
    uint32_t pk = ((uint32_t)__bfloat16_as_ushort(b1) << 16) | __bfloat16_as_ushort(b0);
    size_t o = ((((size_t)layer * 16 + sl) * 4 + mat) * 8 + mgi) * 32 + lane;
    g_w1f[o * 4 + i] = pk;
}

__global__ void prep_w2f(const float* __restrict__ rw, const float* __restrict__ kw) {
    int idx = blockIdx.x * blockDim.x + threadIdx.x;
    if (idx >= NR * 8 * 4 * 8 * 32 * 4) return;
    int i    = idx & 3;
    int lane = (idx >> 2) & 31;
    int mgi  = (idx >> 7) & 7;
    int mat  = (idx >> 10) & 3;
    int sl   = (idx >> 12) & 7;
    int layer = idx >> 15;
    int kc = sl >> 1, ks = sl & 1;
    int row  = mgi * 16 + (lane >> 2) + (i & 1) * 8;
    int kcol = kc * 32 + ks * 16 + (lane & 3) * 2 + ((i >> 1) & 1) * 8;
    const float* src = (mat >> 1) ? kw : rw;
    int half = mat & 1;
    float v0 = src[((size_t)layer * CH + row) * CH + kcol];
    float v1 = src[((size_t)layer * CH + row) * CH + kcol + 1];
    __nv_bfloat16 b0, b1;
    if (half) {
        b0 = __float2bfloat16(v0 - __bfloat162float(__float2bfloat16(v0)));
        b1 = __float2bfloat16(v1 - __bfloat162float(__float2bfloat16(v1)));
    } else {
        b0 = __float2bfloat16(v0);
        b1 = __float2bfloat16(v1);
    }
    uint32_t pk = ((uint32_t)__bfloat16_as_ushort(b1) << 16) | __bfloat16_as_ushort(b0);
    size_t o = ((((size_t)layer * 8 + sl) * 4 + mat) * 8 + mgi) * 32 + lane;
    g_w2f[o * 4 + i] = pk;
}

// ---------------- initial projection ----------------
__global__ void __launch_bounds__(256) proj_kernel(
    const float* __restrict__ x, const float* __restrict__ w0,
    const float* __restrict__ b0, float* __restrict__ h)
{
    __shared__ float xs[CIN][128];
    __shared__ float ws[CH][CIN];
    __shared__ float bs[CH];
    const int b = blockIdx.y, l0 = blockIdx.x * 128, t = threadIdx.x;
    for (int e = t; e < CIN * 128; e += 256) {
        int i = e >> 7, l = e & 127;
        xs[i][l] = x[((size_t)b * CIN + i) * LEN + l0 + l];
    }
    for (int e = t; e < CH * CIN; e += 256) ws[e / CIN][e % CIN] = w0[e];
    if (t < CH) bs[t] = b0[t];
    __syncthreads();
    const int w = t >> 5, lane = t & 31;
    for (int oo = 0; oo < 16; oo++) {
        int o = w * 16 + oo;
        float a0 = bs[o], a1 = bs[o], a2 = bs[o], a3 = bs[o];
        #pragma unroll
        for (int i = 0; i < CIN; i++) {
            float wv = ws[o][i];
            a0 += wv * xs[i][lane];       a1 += wv * xs[i][lane + 32];
            a2 += wv * xs[i][lane + 64];  a3 += wv * xs[i][lane + 96];
        }
        float* dst = h + ((size_t)b * CH + o) * LEN + l0;
        dst[lane] = a0; dst[lane + 32] = a1; dst[lane + 64] = a2; dst[lane + 96] = a3;
    }
}

// ---------------- one WaveNet layer: TL=32, M16xN32 warps, 3 CTAs/SM ----------------
// MERGED: single window of SPAN=32+OFF2 rows, tap1 base = row OFF2-1 (layers 0-4)
// !MERGED: dual 32-row windows, tap1 base = row 32 (layers 5-7)
template<int OFF2, bool MERGED, bool FIRST>
__global__ void __launch_bounds__(THREADS, 3) layer_reg(
    const float* __restrict__ hin, float* __restrict__ hout,
    float* __restrict__ skipout,
    const uint4* __restrict__ w1f, const uint4* __restrict__ w2f,
    const float* __restrict__ csw, const float* __restrict__ cgw,
    const float* __restrict__ z)
{
    constexpr int SPAN = MERGED ? (32 + OFF2) : 64;
    constexpr int T1   = MERGED ? (OFF2 - 1) : 32;
    __shared__ __nv_bfloat16 whi[SPAN * BPITCH];
    __shared__ __nv_bfloat16 wlo[SPAN * BPITCH];

    const int t = threadIdx.x, wid = t >> 5, lane = t & 31;
    const int mg = wid;                                    // 8 M-group warps
    const int b = blockIdx.y, l0 = blockIdx.x * TL;

    // ---- fill window(s): warp w handles channels w*16..w*16+15, fully unrolled ----
    {
        #pragma unroll
        for (int c = 0; c < 16; c++) {
            int ch = wid * 16 + c;
            const float* row = hin + (size_t)(b * CH + ch) * LEN;
            #pragma unroll
            for (int it = 0; it < (SPAN + 31) / 32; it++) {
                int p = lane + it * 32;
                if ((SPAN % 32 == 0) || p < SPAN) {
                    int q;
                    if (MERGED) q = l0 + p - OFF2;
                    else        q = (it == 0) ? (l0 + p - OFF2) : (l0 + (p - 32) - 1);
                    float v = (q >= 0) ? row[q] : 0.f;
                    __nv_bfloat16 h = __float2bfloat16(v);
                    whi[p * BPITCH + ch] = h;
                    wlo[p * BPITCH + ch] = __float2bfloat16(v - __bfloat162float(h));
                }
            }
        }
    }
    __syncthreads();

    float accS[4][4], accG[4][4];
    #pragma unroll
    for (int i = 0; i < 4; i++)
        #pragma unroll
        for (int j = 0; j < 4; j++) { accS[i][j] = 0.f; accG[i][j] = 0.f; }

    const uint32_t b0h_s = sm_u32(whi), b0l_s = sm_u32(wlo);
    const uint32_t b1h_s = b0h_s + (uint32_t)(T1 * BPITCH * 2);
    const uint32_t b1l_s = b0l_s + (uint32_t)(T1 * BPITCH * 2);
    const int ntx   = (lane >> 4) & 1;
    const int khalf = (lane >> 3) & 1;
    const int brow  = lane & 7;
    const uint32_t r0off = (uint32_t)((ntx * 8 + brow) * (BPITCH * 2)) + (uint32_t)(khalf * 16);
    const uint32_t r1off = r0off + 16u * (BPITCH * 2);

    // ---- stage 1: 16 k-slices (tap x kc x ks), A direct from global ----
    const char* wb1 = (const char*)(w1f + (size_t)mg * 32 + lane);
    #pragma unroll
    for (int s = 0; s < 16; s++) {
        const int tap = s >> 3, kc = (s >> 1) & 3, ks = s & 1;
        uint4 aSh = ldg128(wb1 + (size_t)(s * 4 + 0) * 4096);
        uint4 aSl = ldg128(wb1 + (size_t)(s * 4 + 1) * 4096);
        uint4 aGh = ldg128(wb1 + (size_t)(s * 4 + 2) * 4096);
        uint4 aGl = ldg128(wb1 + (size_t)(s * 4 + 3) * 4096);
        const uint32_t bh_s = tap ? b1h_s : b0h_s;
        const uint32_t bl_s = tap ? b1l_s : b0l_s;
        const uint32_t kb = (uint32_t)((kc * 32 + ks * 16) * 2);
        uint32_t bh0[4], bl0[4], bh1[4], bl1[4];
        ldm_x4(bh0, bh_s + r0off + kb);
        ldm_x4(bl0, bl_s + r0off + kb);
        ldm_x4(bh1, bh_s + r1off + kb);
        ldm_x4(bl1, bl_s + r1off + kb);
        #pragma unroll
        for (int hnt = 0; hnt < 2; hnt++) {
            mma16816(accS[hnt], (const uint32_t*)&aSh, bh0 + 2 * hnt);
            mma16816(accG[hnt], (const uint32_t*)&aGh, bh0 + 2 * hnt);
            mma16816(accS[hnt], (const uint32_t*)&aSh, bl0 + 2 * hnt);
            mma16816(accG[hnt], (const uint32_t*)&aGh, bl0 + 2 * hnt);
            mma16816(accS[hnt], (const uint32_t*)&aSl, bh0 + 2 * hnt);
            mma16816(accG[hnt], (const uint32_t*)&aGl, bh0 + 2 * hnt);
        }
        #pragma unroll
        for (int hnt = 0; hnt < 2; hnt++) {
            mma16816(accS[2 + hnt], (const uint32_t*)&aSh, bh1 + 2 * hnt);
            mma16816(accG[2 + hnt], (const uint32_t*)&aGh, bh1 + 2 * hnt);
            mma16816(accS[2 + hnt], (const uint32_t*)&aSh, bl1 + 2 * hnt);
            mma16816(accG[2 + hnt], (const uint32_t*)&aGh, bl1 + 2 * hnt);
            mma16816(accS[2 + hnt], (const uint32_t*)&aSl, bh1 + 2 * hnt);
            mma16816(accG[2 + hnt], (const uint32_t*)&aGl, bh1 + 2 * hnt);
        }
    }

    // ---- conditioning + gating; g -> rows 0..31 of hi/lo window ----
    const int gid = lane >> 2, tig = lane & 3;
    const int ch0 = mg * 16 + gid;
    {
        float cs0 = csw[ch0], cs1 = csw[ch0 + 8];
        float cg0 = cgw[ch0], cg1 = cgw[ch0 + 8];
        const float* zrow = z + (size_t)b * LEN + l0;
        float gv[4][4];
        #pragma unroll
        for (int nt = 0; nt < 4; nt++) {
            int n0 = nt * 8 + tig * 2;
            float z0 = zrow[n0], z1 = zrow[n0 + 1];
            float s0v = accS[nt][0] + cs0 * z0, g0v = accG[nt][0] + cg0 * z0;
            float s1v = accS[nt][1] + cs0 * z1, g1v = accG[nt][1] + cg0 * z1;
            float s2v = accS[nt][2] + cs1 * z0, g2v = accG[nt][2] + cg1 * z0;
            float s3v = accS[nt][3] + cs1 * z1, g3v = accG[nt][3] + cg1 * z1;
            gv[nt][0] = s0v / (1.f + __expf(-g0v));
            gv[nt][1] = s1v / (1.f + __expf(-g1v));
            gv[nt][2] = s2v / (1.f + __expf(-g2v));
            gv[nt][3] = s3v / (1.f + __expf(-g3v));
        }
        __syncthreads();   // all stage-1 window reads complete before overwrite
        #pragma unroll
        for (int nt = 0; nt < 4; nt++) {
            int n0 = nt * 8 + tig * 2;
            #pragma unroll
            for (int j = 0; j < 4; j++) {
                int n  = n0 + (j & 1);
                int ch = ch0 + ((j >> 1) << 3);
                __nv_bfloat16 hi = __float2bfloat16(gv[nt][j]);
                whi[n * BPITCH + ch] = hi;
                wlo[n * BPITCH + ch] = __float2bfloat16(gv[nt][j] - __bfloat162float(hi));
            }
        }
    }
    #pragma unroll
    for (int i = 0; i < 4; i++)
        #pragma unroll
        for (int j = 0; j < 4; j++) { accS[i][j] = 0.f; accG[i][j] = 0.f; }
    __syncthreads();

    // ---- stage 2: res/skip over g (rows 0..31 of window) ----
    const char* wb2 = (const char*)(w2f + (size_t)mg * 32 + lane);
    #pragma unroll
    for (int s = 0; s < 8; s++) {
        const int kc = s >> 1, ks = s & 1;
        uint4 aRh = ldg128(wb2 + (size_t)(s * 4 + 0) * 4096);
        uint4 aRl = ldg128(wb2 + (size_t)(s * 4 + 1) * 4096);
        uint4 aKh = ldg128(wb2 + (size_t)(s * 4 + 2) * 4096);
        uint4 aKl = ldg128(wb2 + (size_t)(s * 4 + 3) * 4096);
        const uint32_t kb = (uint32_t)((kc * 32 + ks * 16) * 2);
        uint32_t bh0[4], bl0[4], bh1[4], bl1[4];
        ldm_x4(bh0, b0h_s + r0off + kb);
        ldm_x4(bl0, b0l_s + r0off + kb);
        ldm_x4(bh1, b0h_s + r1off + kb);
        ldm_x4(bl1, b0l_s + r1off + kb);
        #pragma unroll
        for (int hnt = 0; hnt < 2; hnt++) {
            mma16816(accS[hnt], (const uint32_t*)&aRh, bh0 + 2 * hnt);
            mma16816(accG[hnt], (const uint32_t*)&aKh, bh0 + 2 * hnt);
            mma16816(accS[hnt], (const uint32_t*)&aRh, bl0 + 2 * hnt);
            mma16816(accG[hnt], (const uint32_t*)&aKh, bl0 + 2 * hnt);
            mma16816(accS[hnt], (const uint32_t*)&aRl, bh0 + 2 * hnt);
            mma16816(accG[hnt], (const uint32_t*)&aKl, bh0 + 2 * hnt);
        }
        #pragma unroll
        for (int hnt = 0; hnt < 2; hnt++) {
            mma16816(accS[2 + hnt], (const uint32_t*)&aRh, bh1 + 2 * hnt);
            mma16816(accG[2 + hnt], (const uint32_t*)&aKh, bh1 + 2 * hnt);
            mma16816(accS[2 + hnt], (const uint32_t*)&aRh, bl1 + 2 * hnt);
            mma16816(accG[2 + hnt], (const uint32_t*)&aKh, bl1 + 2 * hnt);
            mma16816(accS[2 + hnt], (const uint32_t*)&aRl, bh1 + 2 * hnt);
            mma16816(accG[2 + hnt], (const uint32_t*)&aKl, bh1 + 2 * hnt);
        }
    }

    // ---- epilogue ----
    #pragma unroll
    for (int nt = 0; nt < 4; nt++) {
        int n0 = nt * 8 + tig * 2;
        #pragma unroll
        for (int j = 0; j < 4; j++) {
            int n  = n0 + (j & 1);
            int ch = ch0 + ((j >> 1) << 3);
            size_t idx = (size_t)(b * CH + ch) * LEN + l0 + n;
            float res = accS[nt][j], sk = accG[nt][j];
            float hv;
            if (FIRST) {
                hv = hin[idx] + res;
            } else {
                float g = __bfloat162float(whi[n * BPITCH + ch]) +
                          __bfloat162float(wlo[n * BPITCH + ch]);
                hv = g + res;
            }
            hout[idx] = hv;
            if (FIRST) skipout[idx] = sk;
            else       skipout[idx] += sk;
        }
    }
}

extern "C" void kernel_launch(void* const* d_in, const int* in_sizes, int n_in,
                              void* d_out, int out_size) {
    (void)in_sizes; (void)n_in; (void)out_size;
    const float* x   = (const float*)d_in[0];
    const float* z   = (const float*)d_in[1];
    const float* w0  = (const float*)d_in[2];
    const float* b0  = (const float*)d_in[3];
    const float* sw  = (const float*)d_in[4];
    const float* gw  = (const float*)d_in[5];
    const float* csw = (const float*)d_in[6];
    const float* cgw = (const float*)d_in[7];
    const float* rw  = (const float*)d_in[8];
    const float* kw  = (const float*)d_in[9];

    float* outH = (float*)d_out;
    float* outS = outH + (size_t)BATCH * CH * LEN;

    float *bufA, *bufB;
    cudaGetSymbolAddress((void**)&bufA, g_bufA);
    cudaGetSymbolAddress((void**)&bufB, g_bufB);
    uint32_t *w1p, *w2p;
    cudaGetSymbolAddress((void**)&w1p, g_w1f);
    cudaGetSymbolAddress((void**)&w2p, g_w2f);

    prep_w1f<<<2048, 256>>>(sw, gw);
    prep_w2f<<<1024, 256>>>(rw, kw);
    proj_kernel<<<dim3(LEN / 128, BATCH), 256>>>(x, w0, b0, bufA);

    const dim3 grid(LEN / TL, BATCH);
    const float* cur = bufA;
    for (int ii = 0; ii < NR; ii++) {
        float* nxt = (ii == NR - 1) ? outH : ((cur == bufA) ? bufB : bufA);
        const uint4* w1 = (const uint4*)(w1p + (size_t)ii * 16 * 4 * 8 * 32 * 4);
        const uint4* w2 = (const uint4*)(w2p + (size_t)ii * 8 * 4 * 8 * 32 * 4);
        const float* cs = csw + ii * CH;
        const float* cg = cgw + ii * CH;
        switch (ii) {
        case 0: layer_reg<2,   true,  true ><<<grid, THREADS>>>(cur, nxt, outS, w1, w2, cs, cg, z); break;
        case 1: layer_reg<3,   true,  false><<<grid, THREADS>>>(cur, nxt, outS, w1, w2, cs, cg, z); break;
        case 2: layer_reg<5,   true,  false><<<grid, THREADS>>>(cur, nxt, outS, w1, w2, cs, cg, z); break;
        case 3: layer_reg<9,   true,  false><<<grid, THREADS>>>(cur, nxt, outS, w1, w2, cs, cg, z); break;
        case 4: layer_reg<17,  true,  false><<<grid, THREADS>>>(cur, nxt, outS, w1, w2, cs, cg, z); break;
        case 5: layer_reg<33,  false, false><<<grid, THREADS>>>(cur, nxt, outS, w1, w2, cs, cg, z); break;
        case 6: layer_reg<65,  false, false><<<grid, THREADS>>>(cur, nxt, outS, w1, w2, cs, cg, z); break;
        case 7: layer_reg<129, false, false><<<grid, THREADS>>>(cur, nxt, outS, w1, w2, cs, cg, z); break;
        }
        cur = nxt;
    }
}

// round 13
// speedup vs baseline: 1.3546x; 1.3055x over previous
#include <cuda_runtime.h>
#include <cuda_bf16.h>
#include <cstdint>

#define BATCH   32
#define CIN     21
#define CH      128
#define LEN     4096
#define NR      8
#define TL      32
#define THREADS 256
#define BPITCH  136      // bf16 per B row; row stride 272B (conflict-free)

// ---------------- device scratch ----------------
__device__ float g_bufA[(size_t)BATCH * CH * LEN];
__device__ float g_bufB[(size_t)BATCH * CH * LEN];
// fragment-major stage1 weights: [layer][slice16: tap,kc,ks][mat4: Sh,Sl,Gh,Gl][mg8][lane32] x uint4
__device__ uint32_t g_w1f[(size_t)NR * 16 * 4 * 8 * 32 * 4];
// stage2: [layer][slice8: kc,ks][mat4: Rh,Rl,Kh,Kl][mg8][lane32] x uint4
__device__ uint32_t g_w2f[(size_t)NR * 8 * 4 * 8 * 32 * 4];

__device__ __forceinline__ uint32_t sm_u32(const void* p) {
    return (uint32_t)__cvta_generic_to_shared(p);
}
__device__ __forceinline__ void ldm_x4(uint32_t* r, uint32_t addr) {
    asm volatile("ldmatrix.sync.aligned.m8n8.x4.shared.b16 {%0,%1,%2,%3}, [%4];"
                 : "=r"(r[0]), "=r"(r[1]), "=r"(r[2]), "=r"(r[3]) : "r"(addr));
}
__device__ __forceinline__ void mma16816(float* c, const uint32_t* a, const uint32_t* b) {
    asm volatile("mma.sync.aligned.m16n8k16.row.col.f32.bf16.bf16.f32 "
                 "{%0,%1,%2,%3}, {%4,%5,%6,%7}, {%8,%9}, {%0,%1,%2,%3};"
                 : "+f"(c[0]), "+f"(c[1]), "+f"(c[2]), "+f"(c[3])
                 : "r"(a[0]), "r"(a[1]), "r"(a[2]), "r"(a[3]),
                   "r"(b[0]), "r"(b[1]));
}
__device__ __forceinline__ uint4 ldg128(const void* p) {
    uint4 v;
    asm volatile("ld.global.nc.v4.u32 {%0,%1,%2,%3}, [%4];"
                 : "=r"(v.x), "=r"(v.y), "=r"(v.z), "=r"(v.w) : "l"(p));
    return v;
}

// ---------------- weight prep: fragment-major, bf16 hi/lo split ----------------
__global__ void prep_w1f(const float* __restrict__ sw, const float* __restrict__ gw) {
    int idx = blockIdx.x * blockDim.x + threadIdx.x;
    if (idx >= NR * 16 * 4 * 8 * 32 * 4) return;
    int i    = idx & 3;
    int lane = (idx >> 2) & 31;
    int mgi  = (idx >> 7) & 7;
    int mat  = (idx >> 10) & 3;
    int sl   = (idx >> 12) & 15;
    int layer = idx >> 16;
    int tap = sl >> 3, kc = (sl >> 1) & 3, ks = sl & 1;
    int row  = mgi * 16 + (lane >> 2) + (i & 1) * 8;
    int kcol = kc * 32 + ks * 16 + (lane & 3) * 2 + ((i >> 1) & 1) * 8;
    const float* src = (mat >> 1) ? gw : sw;
    int half = mat & 1;
    float v0 = src[(((size_t)layer * CH + row) * CH + kcol) * 2 + tap];
    float v1 = src[(((size_t)layer * CH + row) * CH + kcol + 1) * 2 + tap];
    __nv_bfloat16 b0, b1;
    if (half) {
        b0 = __float2bfloat16(v0 - __bfloat162float(__float2bfloat16(v0)));
        b1 = __float2bfloat16(v1 - __bfloat162float(__float2bfloat16(v1)));
    } else {
        b0 = __float2bfloat16(v0);
        b1 = __float2bfloat16(v1);
    }
    uint32_t pk = ((uint32_t)__bfloat16_as_ushort(b1) << 16) | __bfloat16_as_ushort(b0);
    size_t o = ((((size_t)layer * 16 + sl) * 4 + mat) * 8 + mgi) * 32 + lane;
    g_w1f[o * 4 + i] = pk;
}

__global__ void prep_w2f(const float* __restrict__ rw, const float* __restrict__ kw) {
    int idx = blockIdx.x * blockDim.x + threadIdx.x;
    if (idx >= NR * 8 * 4 * 8 * 32 * 4) return;
    int i    = idx & 3;
    int lane = (idx >> 2) & 31;
    int mgi  = (idx >> 7) & 7;
    int mat  = (idx >> 10) & 3;
    int sl   = (idx >> 12) & 7;
    int layer = idx >> 15;
    int kc = sl >> 1, ks = sl & 1;
    int row  = mgi * 16 + (lane >> 2) + (i & 1) * 8;
    int kcol = kc * 32 + ks * 16 + (lane & 3) * 2 + ((i >> 1) & 1) * 8;
    const float* src = (mat >> 1) ? kw : rw;
    int half = mat & 1;
    float v0 = src[((size_t)layer * CH + row) * CH + kcol];
    float v1 = src[((size_t)layer * CH + row) * CH + kcol + 1];
    __nv_bfloat16 b0, b1;
    if (half) {
        b0 = __float2bfloat16(v0 - __bfloat162float(__float2bfloat16(v0)));
        b1 = __float2bfloat16(v1 - __bfloat162float(__float2bfloat16(v1)));
    } else {
        b0 = __float2bfloat16(v0);
        b1 = __float2bfloat16(v1);
    }
    uint32_t pk = ((uint32_t)__bfloat16_as_ushort(b1) << 16) | __bfloat16_as_ushort(b0);
    size_t o = ((((size_t)layer * 8 + sl) * 4 + mat) * 8 + mgi) * 32 + lane;
    g_w2f[o * 4 + i] = pk;
}

// ---------------- initial projection ----------------
__global__ void __launch_bounds__(256) proj_kernel(
    const float* __restrict__ x, const float* __restrict__ w0,
    const float* __restrict__ b0, float* __restrict__ h)
{
    __shared__ float xs[CIN][128];
    __shared__ float ws[CH][CIN];
    __shared__ float bs[CH];
    const int b = blockIdx.y, l0 = blockIdx.x * 128, t = threadIdx.x;
    for (int e = t; e < CIN * 128; e += 256) {
        int i = e >> 7, l = e & 127;
        xs[i][l] = x[((size_t)b * CIN + i) * LEN + l0 + l];
    }
    for (int e = t; e < CH * CIN; e += 256) ws[e / CIN][e % CIN] = w0[e];
    if (t < CH) bs[t] = b0[t];
    __syncthreads();
    const int w = t >> 5, lane = t & 31;
    for (int oo = 0; oo < 16; oo++) {
        int o = w * 16 + oo;
        float a0 = bs[o], a1 = bs[o], a2 = bs[o], a3 = bs[o];
        #pragma unroll
        for (int i = 0; i < CIN; i++) {
            float wv = ws[o][i];
            a0 += wv * xs[i][lane];       a1 += wv * xs[i][lane + 32];
            a2 += wv * xs[i][lane + 64];  a3 += wv * xs[i][lane + 96];
        }
        float* dst = h + ((size_t)b * CH + o) * LEN + l0;
        dst[lane] = a0; dst[lane + 32] = a1; dst[lane + 64] = a2; dst[lane + 96] = a3;
    }
}

// ---------------- one WaveNet layer: TL=32, M16xN32 warps, 3 CTAs/SM ----------------
__global__ void __launch_bounds__(THREADS, 3) layer_reg(
    const float* __restrict__ hin, float* __restrict__ hout,
    float* __restrict__ skipout,
    const uint4* __restrict__ w1f, const uint4* __restrict__ w2f,
    const float* __restrict__ csw, const float* __restrict__ cgw,
    const float* __restrict__ z, int off2, int first)
{
    // two independent 32-row activation windows (tap0: l-off2, tap1: l-1), hi/lo
    __shared__ __nv_bfloat16 b0h[TL * BPITCH];
    __shared__ __nv_bfloat16 b0l[TL * BPITCH];
    __shared__ __nv_bfloat16 b1h[TL * BPITCH];
    __shared__ __nv_bfloat16 b1l[TL * BPITCH];

    const int t = threadIdx.x, wid = t >> 5, lane = t & 31;
    const int mg = wid;                                    // 8 M-group warps
    const int b = blockIdx.y, l0 = blockIdx.x * TL;

    // ---- fill both windows: warp w handles channels w*16..w*16+15, lane = pos ----
    {
        const int p = lane;                                // coalesced LDG
        #pragma unroll
        for (int c = 0; c < 16; c++) {
            int ch = wid * 16 + c;
            const float* row = hin + (size_t)(b * CH + ch) * LEN;
            int q0 = l0 + p - off2, q1 = l0 + p - 1;
            float v0 = (q0 >= 0) ? row[q0] : 0.f;
            float v1 = (q1 >= 0) ? row[q1] : 0.f;
            __nv_bfloat16 h0 = __float2bfloat16(v0);
            __nv_bfloat16 h1 = __float2bfloat16(v1);
            b0h[p * BPITCH + ch] = h0;
            b0l[p * BPITCH + ch] = __float2bfloat16(v0 - __bfloat162float(h0));
            b1h[p * BPITCH + ch] = h1;
            b1l[p * BPITCH + ch] = __float2bfloat16(v1 - __bfloat162float(h1));
        }
    }
    __syncthreads();

    float accS[4][4], accG[4][4];
    #pragma unroll
    for (int i = 0; i < 4; i++)
        #pragma unroll
        for (int j = 0; j < 4; j++) { accS[i][j] = 0.f; accG[i][j] = 0.f; }

    const uint32_t b0h_s = sm_u32(b0h), b0l_s = sm_u32(b0l);
    const uint32_t b1h_s = sm_u32(b1h), b1l_s = sm_u32(b1l);
    const int ntx   = (lane >> 4) & 1;
    const int khalf = (lane >> 3) & 1;
    const int brow  = lane & 7;
    const uint32_t r0off = (uint32_t)((ntx * 8 + brow) * (BPITCH * 2)) + (uint32_t)(khalf * 16);
    const uint32_t r1off = r0off + 16u * (BPITCH * 2);

    // ---- stage 1: 16 k-slices (tap x kc x ks), A direct from global ----
    const char* wb1 = (const char*)(w1f + (size_t)mg * 32 + lane);
    #pragma unroll
    for (int s = 0; s < 16; s++) {
        const int tap = s >> 3, kc = (s >> 1) & 3, ks = s & 1;
        uint4 aSh = ldg128(wb1 + (size_t)(s * 4 + 0) * 4096);
        uint4 aSl = ldg128(wb1 + (size_t)(s * 4 + 1) * 4096);
        uint4 aGh = ldg128(wb1 + (size_t)(s * 4 + 2) * 4096);
        uint4 aGl = ldg128(wb1 + (size_t)(s * 4 + 3) * 4096);
        const uint32_t bh_s = tap ? b1h_s : b0h_s;
        const uint32_t bl_s = tap ? b1l_s : b0l_s;
        const uint32_t kb = (uint32_t)((kc * 32 + ks * 16) * 2);
        uint32_t bh0[4], bl0[4], bh1[4], bl1[4];
        ldm_x4(bh0, bh_s + r0off + kb);
        ldm_x4(bl0, bl_s + r0off + kb);
        ldm_x4(bh1, bh_s + r1off + kb);
        ldm_x4(bl1, bl_s + r1off + kb);
        #pragma unroll
        for (int hnt = 0; hnt < 2; hnt++) {
            mma16816(accS[hnt], (const uint32_t*)&aSh, bh0 + 2 * hnt);
            mma16816(accG[hnt], (const uint32_t*)&aGh, bh0 + 2 * hnt);
            mma16816(accS[hnt], (const uint32_t*)&aSh, bl0 + 2 * hnt);
            mma16816(accG[hnt], (const uint32_t*)&aGh, bl0 + 2 * hnt);
            mma16816(accS[hnt], (const uint32_t*)&aSl, bh0 + 2 * hnt);
            mma16816(accG[hnt], (const uint32_t*)&aGl, bh0 + 2 * hnt);
        }
        #pragma unroll
        for (int hnt = 0; hnt < 2; hnt++) {
            mma16816(accS[2 + hnt], (const uint32_t*)&aSh, bh1 + 2 * hnt);
            mma16816(accG[2 + hnt], (const uint32_t*)&aGh, bh1 + 2 * hnt);
            mma16816(accS[2 + hnt], (const uint32_t*)&aSh, bl1 + 2 * hnt);
            mma16816(accG[2 + hnt], (const uint32_t*)&aGh, bl1 + 2 * hnt);
            mma16816(accS[2 + hnt], (const uint32_t*)&aSl, bh1 + 2 * hnt);
            mma16816(accG[2 + hnt], (const uint32_t*)&aGl, bh1 + 2 * hnt);
        }
    }

    // ---- conditioning + gating; g -> window0 (hi/lo) ----
    const int gid = lane >> 2, tig = lane & 3;
    const int ch0 = mg * 16 + gid;
    {
        float cs0 = csw[ch0], cs1 = csw[ch0 + 8];
        float cg0 = cgw[ch0], cg1 = cgw[ch0 + 8];
        const float* zrow = z + (size_t)b * LEN + l0;
        float gv[4][4];
        #pragma unroll
        for (int nt = 0; nt < 4; nt++) {
            int n0 = nt * 8 + tig * 2;
            float2 zp = *(const float2*)(zrow + n0);
            float s0v = accS[nt][0] + cs0 * zp.x, g0v = accG[nt][0] + cg0 * zp.x;
            float s1v = accS[nt][1] + cs0 * zp.y, g1v = accG[nt][1] + cg0 * zp.y;
            float s2v = accS[nt][2] + cs1 * zp.x, g2v = accG[nt][2] + cg1 * zp.x;
            float s3v = accS[nt][3] + cs1 * zp.y, g3v = accG[nt][3] + cg1 * zp.y;
            gv[nt][0] = s0v / (1.f + __expf(-g0v));
            gv[nt][1] = s1v / (1.f + __expf(-g1v));
            gv[nt][2] = s2v / (1.f + __expf(-g2v));
            gv[nt][3] = s3v / (1.f + __expf(-g3v));
        }
        __syncthreads();   // all stage-1 window reads complete before overwrite
        #pragma unroll
        for (int nt = 0; nt < 4; nt++) {
            int n0 = nt * 8 + tig * 2;
            #pragma unroll
            for (int j = 0; j < 4; j++) {
                int n  = n0 + (j & 1);
                int ch = ch0 + ((j >> 1) << 3);
                __nv_bfloat16 hi = __float2bfloat16(gv[nt][j]);
                b0h[n * BPITCH + ch] = hi;
                b0l[n * BPITCH + ch] = __float2bfloat16(gv[nt][j] - __bfloat162float(hi));
            }
        }
    }
    #pragma unroll
    for (int i = 0; i < 4; i++)
        #pragma unroll
        for (int j = 0; j < 4; j++) { accS[i][j] = 0.f; accG[i][j] = 0.f; }
    __syncthreads();

    // ---- stage 2: res/skip over g (window0 rows 0..31) ----
    const char* wb2 = (const char*)(w2f + (size_t)mg * 32 + lane);
    #pragma unroll
    for (int s = 0; s < 8; s++) {
        const int kc = s >> 1, ks = s & 1;
        uint4 aRh = ldg128(wb2 + (size_t)(s * 4 + 0) * 4096);
        uint4 aRl = ldg128(wb2 + (size_t)(s * 4 + 1) * 4096);
        uint4 aKh = ldg128(wb2 + (size_t)(s * 4 + 2) * 4096);
        uint4 aKl = ldg128(wb2 + (size_t)(s * 4 + 3) * 4096);
        const uint32_t kb = (uint32_t)((kc * 32 + ks * 16) * 2);
        uint32_t bh0[4], bl0[4], bh1[4], bl1[4];
        ldm_x4(bh0, b0h_s + r0off + kb);
        ldm_x4(bl0, b0l_s + r0off + kb);
        ldm_x4(bh1, b0h_s + r1off + kb);
        ldm_x4(bl1, b0l_s + r1off + kb);
        #pragma unroll
        for (int hnt = 0; hnt < 2; hnt++) {
            mma16816(accS[hnt], (const uint32_t*)&aRh, bh0 + 2 * hnt);
            mma16816(accG[hnt], (const uint32_t*)&aKh, bh0 + 2 * hnt);
            mma16816(accS[hnt], (const uint32_t*)&aRh, bl0 + 2 * hnt);
            mma16816(accG[hnt], (const uint32_t*)&aKh, bl0 + 2 * hnt);
            mma16816(accS[hnt], (const uint32_t*)&aRl, bh0 + 2 * hnt);
            mma16816(accG[hnt], (const uint32_t*)&aKl, bh0 + 2 * hnt);
        }
        #pragma unroll
        for (int hnt = 0; hnt < 2; hnt++) {
            mma16816(accS[2 + hnt], (const uint32_t*)&aRh, bh1 + 2 * hnt);
            mma16816(accG[2 + hnt], (const uint32_t*)&aKh, bh1 + 2 * hnt);
            mma16816(accS[2 + hnt], (const uint32_t*)&aRh, bl1 + 2 * hnt);
            mma16816(accG[2 + hnt], (const uint32_t*)&aKh, bl1 + 2 * hnt);
            mma16816(accS[2 + hnt], (const uint32_t*)&aRl, bh1 + 2 * hnt);
            mma16816(accG[2 + hnt], (const uint32_t*)&aKl, bh1 + 2 * hnt);
        }
    }

    // ---- epilogue: vectorized float2 writes (n0, n0+1 adjacent; idx even) ----
    #pragma unroll
    for (int nt = 0; nt < 4; nt++) {
        int n0 = nt * 8 + tig * 2;
        #pragma unroll
        for (int hf = 0; hf < 2; hf++) {
            int ch = ch0 + hf * 8;
            size_t idx = (size_t)(b * CH + ch) * LEN + l0 + n0;
            float r0 = accS[nt][hf * 2 + 0], r1 = accS[nt][hf * 2 + 1];
            float k0 = accG[nt][hf * 2 + 0], k1 = accG[nt][hf * 2 + 1];
            float2 hv;
            if (first) {
                float2 hi2 = *(const float2*)(hin + idx);
                hv.x = hi2.x + r0;
                hv.y = hi2.y + r1;
            } else {
                hv.x = __bfloat162float(b0h[n0 * BPITCH + ch]) +
                       __bfloat162float(b0l[n0 * BPITCH + ch]) + r0;
                hv.y = __bfloat162float(b0h[(n0 + 1) * BPITCH + ch]) +
                       __bfloat162float(b0l[(n0 + 1) * BPITCH + ch]) + r1;
            }
            *(float2*)(hout + idx) = hv;
            if (first) {
                *(float2*)(skipout + idx) = make_float2(k0, k1);
            } else {
                float2 sp = *(const float2*)(skipout + idx);
                sp.x += k0;
                sp.y += k1;
                *(float2*)(skipout + idx) = sp;
            }
        }
    }
}

extern "C" void kernel_launch(void* const* d_in, const int* in_sizes, int n_in,
                              void* d_out, int out_size) {
    (void)in_sizes; (void)n_in; (void)out_size;
    const float* x   = (const float*)d_in[0];
    const float* z   = (const float*)d_in[1];
    const float* w0  = (const float*)d_in[2];
    const float* b0  = (const float*)d_in[3];
    const float* sw  = (const float*)d_in[4];
    const float* gw  = (const float*)d_in[5];
    const float* csw = (const float*)d_in[6];
    const float* cgw = (const float*)d_in[7];
    const float* rw  = (const float*)d_in[8];
    const float* kw  = (const float*)d_in[9];

    float* outH = (float*)d_out;
    float* outS = outH + (size_t)BATCH * CH * LEN;

    float *bufA, *bufB;
    cudaGetSymbolAddress((void**)&bufA, g_bufA);
    cudaGetSymbolAddress((void**)&bufB, g_bufB);
    uint32_t *w1p, *w2p;
    cudaGetSymbolAddress((void**)&w1p, g_w1f);
    cudaGetSymbolAddress((void**)&w2p, g_w2f);

    prep_w1f<<<2048, 256>>>(sw, gw);
    prep_w2f<<<1024, 256>>>(rw, kw);
    proj_kernel<<<dim3(LEN / 128, BATCH), 256>>>(x, w0, b0, bufA);

    const float* cur = bufA;
    for (int ii = 0; ii < NR; ii++) {
        int d    = 1 << ii;
        int off2 = (ii == 0) ? 2 : d + 1;
        float* nxt = (ii == NR - 1) ? outH : ((cur == bufA) ? bufB : bufA);
        layer_reg<<<dim3(LEN / TL, BATCH), THREADS>>>(
            cur, nxt, outS,
            (const uint4*)(w1p + (size_t)ii * 16 * 4 * 8 * 32 * 4),
            (const uint4*)(w2p + (size_t)ii * 8 * 4 * 8 * 32 * 4),
            csw + ii * CH, cgw + ii * CH,
            z, off2, ii == 0 ? 1 : 0);
        cur = nxt;
    }
}

// round 14
// speedup vs baseline: 1.3844x; 1.0220x over previous
#include <cuda_runtime.h>
#include <cuda_bf16.h>
#include <cstdint>

#define BATCH   32
#define CIN     21
#define CH      128
#define LEN     4096
#define NR      8
#define TL      32
#define THREADS 256
#define BPITCH  136      // bf16 per B row; row stride 272B (conflict-free)
#define GXP     34       // Gx fp32 pitch (even -> float2 aligned)

// ---------------- device scratch ----------------
__device__ float g_bufA[(size_t)BATCH * CH * LEN];
__device__ float g_bufB[(size_t)BATCH * CH * LEN];
// fragment-major stage1 weights: [layer][slice16: tap,kc,ks][mat4: Sh,Sl,Gh,Gl][mg8][lane32] x uint4
__device__ uint32_t g_w1f[(size_t)NR * 16 * 4 * 8 * 32 * 4];
// stage2: [layer][slice8: kc,ks][mat4: Rh,Rl,Kh,Kl][mg8][lane32] x uint4
__device__ uint32_t g_w2f[(size_t)NR * 8 * 4 * 8 * 32 * 4];

__device__ __forceinline__ uint32_t sm_u32(const void* p) {
    return (uint32_t)__cvta_generic_to_shared(p);
}
__device__ __forceinline__ void ldm_x4(uint32_t* r, uint32_t addr) {
    asm volatile("ldmatrix.sync.aligned.m8n8.x4.shared.b16 {%0,%1,%2,%3}, [%4];"
                 : "=r"(r[0]), "=r"(r[1]), "=r"(r[2]), "=r"(r[3]) : "r"(addr));
}
__device__ __forceinline__ void mma16816(float* c, const uint32_t* a, const uint32_t* b) {
    asm volatile("mma.sync.aligned.m16n8k16.row.col.f32.bf16.bf16.f32 "
                 "{%0,%1,%2,%3}, {%4,%5,%6,%7}, {%8,%9}, {%0,%1,%2,%3};"
                 : "+f"(c[0]), "+f"(c[1]), "+f"(c[2]), "+f"(c[3])
                 : "r"(a[0]), "r"(a[1]), "r"(a[2]), "r"(a[3]),
                   "r"(b[0]), "r"(b[1]));
}
__device__ __forceinline__ uint4 ldg128(const void* p) {
    uint4 v;
    asm volatile("ld.global.nc.v4.u32 {%0,%1,%2,%3}, [%4];"
                 : "=r"(v.x), "=r"(v.y), "=r"(v.z), "=r"(v.w) : "l"(p));
    return v;
}
__device__ __forceinline__ uint32_t pkbf2(float a, float b) {
    __nv_bfloat16 ba = __float2bfloat16(a), bb = __float2bfloat16(b);
    return ((uint32_t)__bfloat16_as_ushort(bb) << 16) | __bfloat16_as_ushort(ba);
}

// ---------------- weight prep: fragment-major, bf16 hi/lo split ----------------
__global__ void prep_w1f(const float* __restrict__ sw, const float* __restrict__ gw) {
    int idx = blockIdx.x * blockDim.x + threadIdx.x;
    if (idx >= NR * 16 * 4 * 8 * 32 * 4) return;
    int i    = idx & 3;
    int lane = (idx >> 2) & 31;
    int mgi  = (idx >> 7) & 7;
    int mat  = (idx >> 10) & 3;
    int sl   = (idx >> 12) & 15;
    int layer = idx >> 16;
    int tap = sl >> 3, kc = (sl >> 1) & 3, ks = sl & 1;
    int row  = mgi * 16 + (lane >> 2) + (i & 1) * 8;
    int kcol = kc * 32 + ks * 16 + (lane & 3) * 2 + ((i >> 1) & 1) * 8;
    const float* src = (mat >> 1) ? gw : sw;
    int half = mat & 1;
    float v0 = src[(((size_t)layer * CH + row) * CH + kcol) * 2 + tap];
    float v1 = src[(((size_t)layer * CH + row) * CH + kcol + 1) * 2 + tap];
    __nv_bfloat16 b0, b1;
    if (half) {
        b0 = __float2bfloat16(v0 - __bfloat162float(__float2bfloat16(v0)));
        b1 = __float2bfloat16(v1 - __bfloat162float(__float2bfloat16(v1)));
    } else {
        b0 = __float2bfloat16(v0);
        b1 = __float2bfloat16(v1);
    }
    uint32_t pk = ((uint32_t)__bfloat16_as_ushort(b1) << 16) | __bfloat16_as_ushort(b0);
    size_t o = ((((size_t)layer * 16 + sl) * 4 + mat) * 8 + mgi) * 32 + lane;
    g_w1f[o * 4 + i] = pk;
}

__global__ void prep_w2f(const float* __restrict__ rw, const float* __restrict__ kw) {
    int idx = blockIdx.x * blockDim.x + threadIdx.x;
    if (idx >= NR * 8 * 4 * 8 * 32 * 4) return;
    int i    = idx & 3;
    int lane = (idx >> 2) & 31;
    int mgi  = (idx >> 7) & 7;
    int mat  = (idx >> 10) & 3;
    int sl   = (idx >> 12) & 7;
    int layer = idx >> 15;
    int kc = sl >> 1, ks = sl & 1;
    int row  = mgi * 16 + (lane >> 2) + (i & 1) * 8;
    int kcol = kc * 32 + ks * 16 + (lane & 3) * 2 + ((i >> 1) & 1) * 8;
    const float* src = (mat >> 1) ? kw : rw;
    int half = mat & 1;
    float v0 = src[((size_t)layer * CH + row) * CH + kcol];
    float v1 = src[((size_t)layer * CH + row) * CH + kcol + 1];
    __nv_bfloat16 b0, b1;
    if (half) {
        b0 = __float2bfloat16(v0 - __bfloat162float(__float2bfloat16(v0)));
        b1 = __float2bfloat16(v1 - __bfloat162float(__float2bfloat16(v1)));
    } else {
        b0 = __float2bfloat16(v0);
        b1 = __float2bfloat16(v1);
    }
    uint32_t pk = ((uint32_t)__bfloat16_as_ushort(b1) << 16) | __bfloat16_as_ushort(b0);
    size_t o = ((((size_t)layer * 8 + sl) * 4 + mat) * 8 + mgi) * 32 + lane;
    g_w2f[o * 4 + i] = pk;
}

// ---------------- initial projection ----------------
__global__ void __launch_bounds__(256) proj_kernel(
    const float* __restrict__ x, const float* __restrict__ w0,
    const float* __restrict__ b0, float* __restrict__ h)
{
    __shared__ float xs[CIN][128];
    __shared__ float ws[CH][CIN];
    __shared__ float bs[CH];
    const int b = blockIdx.y, l0 = blockIdx.x * 128, t = threadIdx.x;
    for (int e = t; e < CIN * 128; e += 256) {
        int i = e >> 7, l = e & 127;
        xs[i][l] = x[((size_t)b * CIN + i) * LEN + l0 + l];
    }
    for (int e = t; e < CH * CIN; e += 256) ws[e / CIN][e % CIN] = w0[e];
    if (t < CH) bs[t] = b0[t];
    __syncthreads();
    const int w = t >> 5, lane = t & 31;
    for (int oo = 0; oo < 16; oo++) {
        int o = w * 16 + oo;
        float a0 = bs[o], a1 = bs[o], a2 = bs[o], a3 = bs[o];
        #pragma unroll
        for (int i = 0; i < CIN; i++) {
            float wv = ws[o][i];
            a0 += wv * xs[i][lane];       a1 += wv * xs[i][lane + 32];
            a2 += wv * xs[i][lane + 64];  a3 += wv * xs[i][lane + 96];
        }
        float* dst = h + ((size_t)b * CH + o) * LEN + l0;
        dst[lane] = a0; dst[lane + 32] = a1; dst[lane + 64] = a2; dst[lane + 96] = a3;
    }
}

// ---------------- one WaveNet layer: TL=32, M16xN32 warps, 3 CTAs/SM ----------------
__global__ void __launch_bounds__(THREADS, 3) layer_reg(
    const float* __restrict__ hin, float* __restrict__ hout,
    float* __restrict__ skipout,
    const uint4* __restrict__ w1f, const uint4* __restrict__ w2f,
    const float* __restrict__ csw, const float* __restrict__ cgw,
    const float* __restrict__ z, int off2, int first)
{
    // combined window buffer: [b0h | b0l | b1h | b1l], each [32][BPITCH] bf16.
    // After stage 1, the b1 region is reused as Gx: fp32 g, [128][GXP].
    __shared__ __nv_bfloat16 win[4 * TL * BPITCH];
    __nv_bfloat16* b0h = win;
    __nv_bfloat16* b0l = win + TL * BPITCH;
    __nv_bfloat16* b1h = win + 2 * TL * BPITCH;
    __nv_bfloat16* b1l = win + 3 * TL * BPITCH;
    float* Gx = (float*)(win + 2 * TL * BPITCH);   // 128*GXP*4 = 17408 B = b1 size

    const int t = threadIdx.x, wid = t >> 5, lane = t & 31;
    const int mg = wid;                                    // 8 M-group warps
    const int b = blockIdx.y, l0 = blockIdx.x * TL;

    // ---- fill both windows: 4-channel packed STS.64, lane = pos ----
    {
        const int p = lane;
        const int q0 = l0 + p - off2, q1 = l0 + p - 1;
        #pragma unroll
        for (int cc = 0; cc < 4; cc++) {
            const int ch0 = wid * 16 + cc * 4;
            float v0[4], v1[4];
            #pragma unroll
            for (int k = 0; k < 4; k++) {
                const float* row = hin + (size_t)(b * CH + ch0 + k) * LEN;
                v0[k] = (q0 >= 0) ? row[q0] : 0.f;
                v1[k] = (q1 >= 0) ? row[q1] : 0.f;
            }
            uint2 h0v, l0v, h1v, l1v;
            h0v.x = pkbf2(v0[0], v0[1]);  h0v.y = pkbf2(v0[2], v0[3]);
            l0v.x = pkbf2(v0[0] - __bfloat162float(__float2bfloat16(v0[0])),
                          v0[1] - __bfloat162float(__float2bfloat16(v0[1])));
            l0v.y = pkbf2(v0[2] - __bfloat162float(__float2bfloat16(v0[2])),
                          v0[3] - __bfloat162float(__float2bfloat16(v0[3])));
            h1v.x = pkbf2(v1[0], v1[1]);  h1v.y = pkbf2(v1[2], v1[3]);
            l1v.x = pkbf2(v1[0] - __bfloat162float(__float2bfloat16(v1[0])),
                          v1[1] - __bfloat162float(__float2bfloat16(v1[1])));
            l1v.y = pkbf2(v1[2] - __bfloat162float(__float2bfloat16(v1[2])),
                          v1[3] - __bfloat162float(__float2bfloat16(v1[3])));
            *(uint2*)&b0h[p * BPITCH + ch0] = h0v;
            *(uint2*)&b0l[p * BPITCH + ch0] = l0v;
            *(uint2*)&b1h[p * BPITCH + ch0] = h1v;
            *(uint2*)&b1l[p * BPITCH + ch0] = l1v;
        }
    }
    __syncthreads();

    float accS[4][4], accG[4][4];
    #pragma unroll
    for (int i = 0; i < 4; i++)
        #pragma unroll
        for (int j = 0; j < 4; j++) { accS[i][j] = 0.f; accG[i][j] = 0.f; }

    const uint32_t b0h_s = sm_u32(b0h), b0l_s = sm_u32(b0l);
    const uint32_t b1h_s = sm_u32(b1h), b1l_s = sm_u32(b1l);
    const int ntx   = (lane >> 4) & 1;
    const int khalf = (lane >> 3) & 1;
    const int brow  = lane & 7;
    const uint32_t r0off = (uint32_t)((ntx * 8 + brow) * (BPITCH * 2)) + (uint32_t)(khalf * 16);
    const uint32_t r1off = r0off + 16u * (BPITCH * 2);

    // ---- stage 1: 16 k-slices (tap x kc x ks), A direct from global ----
    const char* wb1 = (const char*)(w1f + (size_t)mg * 32 + lane);
    #pragma unroll
    for (int s = 0; s < 16; s++) {
        const int tap = s >> 3, kc = (s >> 1) & 3, ks = s & 1;
        uint4 aSh = ldg128(wb1 + (size_t)(s * 4 + 0) * 4096);
        uint4 aSl = ldg128(wb1 + (size_t)(s * 4 + 1) * 4096);
        uint4 aGh = ldg128(wb1 + (size_t)(s * 4 + 2) * 4096);
        uint4 aGl = ldg128(wb1 + (size_t)(s * 4 + 3) * 4096);
        const uint32_t bh_s = tap ? b1h_s : b0h_s;
        const uint32_t bl_s = tap ? b1l_s : b0l_s;
        const uint32_t kb = (uint32_t)((kc * 32 + ks * 16) * 2);
        uint32_t bh0[4], bl0[4], bh1[4], bl1[4];
        ldm_x4(bh0, bh_s + r0off + kb);
        ldm_x4(bl0, bl_s + r0off + kb);
        ldm_x4(bh1, bh_s + r1off + kb);
        ldm_x4(bl1, bl_s + r1off + kb);
        #pragma unroll
        for (int hnt = 0; hnt < 2; hnt++) {
            mma16816(accS[hnt], (const uint32_t*)&aSh, bh0 + 2 * hnt);
            mma16816(accG[hnt], (const uint32_t*)&aGh, bh0 + 2 * hnt);
            mma16816(accS[hnt], (const uint32_t*)&aSh, bl0 + 2 * hnt);
            mma16816(accG[hnt], (const uint32_t*)&aGh, bl0 + 2 * hnt);
            mma16816(accS[hnt], (const uint32_t*)&aSl, bh0 + 2 * hnt);
            mma16816(accG[hnt], (const uint32_t*)&aGl, bh0 + 2 * hnt);
        }
        #pragma unroll
        for (int hnt = 0; hnt < 2; hnt++) {
            mma16816(accS[2 + hnt], (const uint32_t*)&aSh, bh1 + 2 * hnt);
            mma16816(accG[2 + hnt], (const uint32_t*)&aGh, bh1 + 2 * hnt);
            mma16816(accS[2 + hnt], (const uint32_t*)&aSh, bl1 + 2 * hnt);
            mma16816(accG[2 + hnt], (const uint32_t*)&aGh, bl1 + 2 * hnt);
            mma16816(accS[2 + hnt], (const uint32_t*)&aSl, bh1 + 2 * hnt);
            mma16816(accG[2 + hnt], (const uint32_t*)&aGl, bh1 + 2 * hnt);
        }
    }

    // ---- conditioning + gating; g -> window0 (bf16 hi/lo) + Gx (fp32) ----
    const int gid = lane >> 2, tig = lane & 3;
    const int ch0 = mg * 16 + gid;
    {
        float cs0 = csw[ch0], cs1 = csw[ch0 + 8];
        float cg0 = cgw[ch0], cg1 = cgw[ch0 + 8];
        const float* zrow = z + (size_t)b * LEN + l0;
        float gv[4][4];
        #pragma unroll
        for (int nt = 0; nt < 4; nt++) {
            int n0 = nt * 8 + tig * 2;
            float2 zp = *(const float2*)(zrow + n0);
            float s0v = accS[nt][0] + cs0 * zp.x, g0v = accG[nt][0] + cg0 * zp.x;
            float s1v = accS[nt][1] + cs0 * zp.y, g1v = accG[nt][1] + cg0 * zp.y;
            float s2v = accS[nt][2] + cs1 * zp.x, g2v = accG[nt][2] + cg1 * zp.x;
            float s3v = accS[nt][3] + cs1 * zp.y, g3v = accG[nt][3] + cg1 * zp.y;
            gv[nt][0] = s0v / (1.f + __expf(-g0v));
            gv[nt][1] = s1v / (1.f + __expf(-g1v));
            gv[nt][2] = s2v / (1.f + __expf(-g2v));
            gv[nt][3] = s3v / (1.f + __expf(-g3v));
        }
        __syncthreads();   // all stage-1 window reads complete before overwrite
        #pragma unroll
        for (int nt = 0; nt < 4; nt++) {
            int n0 = nt * 8 + tig * 2;
            // bf16 hi/lo for stage-2 B operand
            #pragma unroll
            for (int j = 0; j < 4; j++) {
                int n  = n0 + (j & 1);
                int ch = ch0 + ((j >> 1) << 3);
                __nv_bfloat16 hi = __float2bfloat16(gv[nt][j]);
                b0h[n * BPITCH + ch] = hi;
                b0l[n * BPITCH + ch] = __float2bfloat16(gv[nt][j] - __bfloat162float(hi));
            }
            // fp32 g for the epilogue (Gx[ch][n], float2 per (ch, n-pair))
            *(float2*)&Gx[ch0 * GXP + n0]       = make_float2(gv[nt][0], gv[nt][1]);
            *(float2*)&Gx[(ch0 + 8) * GXP + n0] = make_float2(gv[nt][2], gv[nt][3]);
        }
    }
    #pragma unroll
    for (int i = 0; i < 4; i++)
        #pragma unroll
        for (int j = 0; j < 4; j++) { accS[i][j] = 0.f; accG[i][j] = 0.f; }
    __syncthreads();

    // ---- stage 2: res/skip over g (window0 rows 0..31) ----
    const char* wb2 = (const char*)(w2f + (size_t)mg * 32 + lane);
    #pragma unroll
    for (int s = 0; s < 8; s++) {
        const int kc = s >> 1, ks = s & 1;
        uint4 aRh = ldg128(wb2 + (size_t)(s * 4 + 0) * 4096);
        uint4 aRl = ldg128(wb2 + (size_t)(s * 4 + 1) * 4096);
        uint4 aKh = ldg128(wb2 + (size_t)(s * 4 + 2) * 4096);
        uint4 aKl = ldg128(wb2 + (size_t)(s * 4 + 3) * 4096);
        const uint32_t kb = (uint32_t)((kc * 32 + ks * 16) * 2);
        uint32_t bh0[4], bl0[4], bh1[4], bl1[4];
        ldm_x4(bh0, b0h_s + r0off + kb);
        ldm_x4(bl0, b0l_s + r0off + kb);
        ldm_x4(bh1, b0h_s + r1off + kb);
        ldm_x4(bl1, b0l_s + r1off + kb);
        #pragma unroll
        for (int hnt = 0; hnt < 2; hnt++) {
            mma16816(accS[hnt], (const uint32_t*)&aRh, bh0 + 2 * hnt);
            mma16816(accG[hnt], (const uint32_t*)&aKh, bh0 + 2 * hnt);
            mma16816(accS[hnt], (const uint32_t*)&aRh, bl0 + 2 * hnt);
            mma16816(accG[hnt], (const uint32_t*)&aKh, bl0 + 2 * hnt);
            mma16816(accS[hnt], (const uint32_t*)&aRl, bh0 + 2 * hnt);
            mma16816(accG[hnt], (const uint32_t*)&aKl, bh0 + 2 * hnt);
        }
        #pragma unroll
        for (int hnt = 0; hnt < 2; hnt++) {
            mma16816(accS[2 + hnt], (const uint32_t*)&aRh, bh1 + 2 * hnt);
            mma16816(accG[2 + hnt], (const uint32_t*)&aKh, bh1 + 2 * hnt);
            mma16816(accS[2 + hnt], (const uint32_t*)&aRh, bl1 + 2 * hnt);
            mma16816(accG[2 + hnt], (const uint32_t*)&aKh, bl1 + 2 * hnt);
            mma16816(accS[2 + hnt], (const uint32_t*)&aRl, bh1 + 2 * hnt);
            mma16816(accG[2 + hnt], (const uint32_t*)&aKl, bh1 + 2 * hnt);
        }
    }

    // ---- epilogue: vectorized float2; g from Gx (fp32) ----
    #pragma unroll
    for (int nt = 0; nt < 4; nt++) {
        int n0 = nt * 8 + tig * 2;
        #pragma unroll
        for (int hf = 0; hf < 2; hf++) {
            int ch = ch0 + hf * 8;
            size_t idx = (size_t)(b * CH + ch) * LEN + l0 + n0;
            float r0 = accS[nt][hf * 2 + 0], r1 = accS[nt][hf * 2 + 1];
            float k0 = accG[nt][hf * 2 + 0], k1 = accG[nt][hf * 2 + 1];
            float2 hv;
            if (first) {
                float2 hi2 = *(const float2*)(hin + idx);
                hv.x = hi2.x + r0;
                hv.y = hi2.y + r1;
            } else {
                float2 gp = *(const float2*)&Gx[ch * GXP + n0];
                hv.x = gp.x + r0;
                hv.y = gp.y + r1;
            }
            *(float2*)(hout + idx) = hv;
            if (first) {
                *(float2*)(skipout + idx) = make_float2(k0, k1);
            } else {
                float2 sp = *(const float2*)(skipout + idx);
                sp.x += k0;
                sp.y += k1;
                *(float2*)(skipout + idx) = sp;
            }
        }
    }
}

extern "C" void kernel_launch(void* const* d_in, const int* in_sizes, int n_in,
                              void* d_out, int out_size) {
    (void)in_sizes; (void)n_in; (void)out_size;
    const float* x   = (const float*)d_in[0];
    const float* z   = (const float*)d_in[1];
    const float* w0  = (const float*)d_in[2];
    const float* b0  = (const float*)d_in[3];
    const float* sw  = (const float*)d_in[4];
    const float* gw  = (const float*)d_in[5];
    const float* csw = (const float*)d_in[6];
    const float* cgw = (const float*)d_in[7];
    const float* rw  = (const float*)d_in[8];
    const float* kw  = (const float*)d_in[9];

    float* outH = (float*)d_out;
    float* outS = outH + (size_t)BATCH * CH * LEN;

    float *bufA, *bufB;
    cudaGetSymbolAddress((void**)&bufA, g_bufA);
    cudaGetSymbolAddress((void**)&bufB, g_bufB);
    uint32_t *w1p, *w2p;
    cudaGetSymbolAddress((void**)&w1p, g_w1f);
    cudaGetSymbolAddress((void**)&w2p, g_w2f);

    prep_w1f<<<2048, 256>>>(sw, gw);
    prep_w2f<<<1024, 256>>>(rw, kw);
    proj_kernel<<<dim3(LEN / 128, BATCH), 256>>>(x, w0, b0, bufA);

    const float* cur = bufA;
    for (int ii = 0; ii < NR; ii++) {
        int d    = 1 << ii;
        int off2 = (ii == 0) ? 2 : d + 1;
        float* nxt = (ii == NR - 1) ? outH : ((cur == bufA) ? bufB : bufA);
        layer_reg<<<dim3(LEN / TL, BATCH), THREADS>>>(
            cur, nxt, outS,
            (const uint4*)(w1p + (size_t)ii * 16 * 4 * 8 * 32 * 4),
            (const uint4*)(w2p + (size_t)ii * 8 * 4 * 8 * 32 * 4),
            csw + ii * CH, cgw + ii * CH,
            z, off2, ii == 0 ? 1 : 0);
        cur = nxt;
    }
}

// round 15
// speedup vs baseline: 1.3893x; 1.0036x over previous
#include <cuda_runtime.h>
#include <cuda_bf16.h>
#include <cstdint>

#define BATCH   32
#define CIN     21
#define CH      128
#define LEN     4096
#define NR      8
#define TL      32
#define THREADS 256
#define BPITCH  136      // bf16 per B row; row stride 272B (conflict-free)
#define GXP     34       // Gx fp32 pitch (even -> float2 aligned)

// ---------------- device scratch ----------------
__device__ float g_bufA[(size_t)BATCH * CH * LEN];
__device__ float g_bufB[(size_t)BATCH * CH * LEN];
// fragment-major stage1 weights: [layer][slice16: tap,kc,ks][mat4: Sh,Sl,Gh,Gl][mg8][lane32] x uint4
__device__ uint32_t g_w1f[(size_t)NR * 16 * 4 * 8 * 32 * 4];
// stage2: [layer][slice8: kc,ks][mat4: Rh,Rl,Kh,Kl][mg8][lane32] x uint4
__device__ uint32_t g_w2f[(size_t)NR * 8 * 4 * 8 * 32 * 4];

__device__ __forceinline__ uint32_t sm_u32(const void* p) {
    return (uint32_t)__cvta_generic_to_shared(p);
}
__device__ __forceinline__ void ldm_x4(uint32_t* r, uint32_t addr) {
    asm volatile("ldmatrix.sync.aligned.m8n8.x4.shared.b16 {%0,%1,%2,%3}, [%4];"
                 : "=r"(r[0]), "=r"(r[1]), "=r"(r[2]), "=r"(r[3]) : "r"(addr));
}
__device__ __forceinline__ void mma16816(float* c, const uint32_t* a, const uint32_t* b) {
    asm volatile("mma.sync.aligned.m16n8k16.row.col.f32.bf16.bf16.f32 "
                 "{%0,%1,%2,%3}, {%4,%5,%6,%7}, {%8,%9}, {%0,%1,%2,%3};"
                 : "+f"(c[0]), "+f"(c[1]), "+f"(c[2]), "+f"(c[3])
                 : "r"(a[0]), "r"(a[1]), "r"(a[2]), "r"(a[3]),
                   "r"(b[0]), "r"(b[1]));
}
__device__ __forceinline__ uint4 ldg128(const void* p) {
    uint4 v;
    asm volatile("ld.global.nc.v4.u32 {%0,%1,%2,%3}, [%4];"
                 : "=r"(v.x), "=r"(v.y), "=r"(v.z), "=r"(v.w) : "l"(p));
    return v;
}
__device__ __forceinline__ uint32_t pkbf2(float a, float b) {
    __nv_bfloat16 ba = __float2bfloat16(a), bb = __float2bfloat16(b);
    return ((uint32_t)__bfloat16_as_ushort(bb) << 16) | __bfloat16_as_ushort(ba);
}

// ---------------- weight prep: fragment-major, bf16 hi/lo split ----------------
__global__ void prep_w1f(const float* __restrict__ sw, const float* __restrict__ gw) {
    int idx = blockIdx.x * blockDim.x + threadIdx.x;
    if (idx >= NR * 16 * 4 * 8 * 32 * 4) return;
    int i    = idx & 3;
    int lane = (idx >> 2) & 31;
    int mgi  = (idx >> 7) & 7;
    int mat  = (idx >> 10) & 3;
    int sl   = (idx >> 12) & 15;
    int layer = idx >> 16;
    int tap = sl >> 3, kc = (sl >> 1) & 3, ks = sl & 1;
    int row  = mgi * 16 + (lane >> 2) + (i & 1) * 8;
    int kcol = kc * 32 + ks * 16 + (lane & 3) * 2 + ((i >> 1) & 1) * 8;
    const float* src = (mat >> 1) ? gw : sw;
    int half = mat & 1;
    float v0 = src[(((size_t)layer * CH + row) * CH + kcol) * 2 + tap];
    float v1 = src[(((size_t)layer * CH + row) * CH + kcol + 1) * 2 + tap];
    __nv_bfloat16 b0, b1;
    if (half) {
        b0 = __float2bfloat16(v0 - __bfloat162float(__float2bfloat16(v0)));
        b1 = __float2bfloat16(v1 - __bfloat162float(__float2bfloat16(v1)));
    } else {
        b0 = __float2bfloat16(v0);
        b1 = __float2bfloat16(v1);
    }
    uint32_t pk = ((uint32_t)__bfloat16_as_ushort(b1) << 16) | __bfloat16_as_ushort(b0);
    size_t o = ((((size_t)layer * 16 + sl) * 4 + mat) * 8 + mgi) * 32 + lane;
    g_w1f[o * 4 + i] = pk;
}

__global__ void prep_w2f(const float* __restrict__ rw, const float* __restrict__ kw) {
    int idx = blockIdx.x * blockDim.x + threadIdx.x;
    if (idx >= NR * 8 * 4 * 8 * 32 * 4) return;
    int i    = idx & 3;
    int lane = (idx >> 2) & 31;
    int mgi  = (idx >> 7) & 7;
    int mat  = (idx >> 10) & 3;
    int sl   = (idx >> 12) & 7;
    int layer = idx >> 15;
    int kc = sl >> 1, ks = sl & 1;
    int row  = mgi * 16 + (lane >> 2) + (i & 1) * 8;
    int kcol = kc * 32 + ks * 16 + (lane & 3) * 2 + ((i >> 1) & 1) * 8;
    const float* src = (mat >> 1) ? kw : rw;
    int half = mat & 1;
    float v0 = src[((size_t)layer * CH + row) * CH + kcol];
    float v1 = src[((size_t)layer * CH + row) * CH + kcol + 1];
    __nv_bfloat16 b0, b1;
    if (half) {
        b0 = __float2bfloat16(v0 - __bfloat162float(__float2bfloat16(v0)));
        b1 = __float2bfloat16(v1 - __bfloat162float(__float2bfloat16(v1)));
    } else {
        b0 = __float2bfloat16(v0);
        b1 = __float2bfloat16(v1);
    }
    uint32_t pk = ((uint32_t)__bfloat16_as_ushort(b1) << 16) | __bfloat16_as_ushort(b0);
    size_t o = ((((size_t)layer * 8 + sl) * 4 + mat) * 8 + mgi) * 32 + lane;
    g_w2f[o * 4 + i] = pk;
}

// ---------------- initial projection ----------------
__global__ void __launch_bounds__(256) proj_kernel(
    const float* __restrict__ x, const float* __restrict__ w0,
    const float* __restrict__ b0, float* __restrict__ h)
{
    __shared__ float xs[CIN][128];
    __shared__ float ws[CH][CIN];
    __shared__ float bs[CH];
    const int b = blockIdx.y, l0 = blockIdx.x * 128, t = threadIdx.x;
    for (int e = t; e < CIN * 128; e += 256) {
        int i = e >> 7, l = e & 127;
        xs[i][l] = x[((size_t)b * CIN + i) * LEN + l0 + l];
    }
    for (int e = t; e < CH * CIN; e += 256) ws[e / CIN][e % CIN] = w0[e];
    if (t < CH) bs[t] = b0[t];
    __syncthreads();
    const int w = t >> 5, lane = t & 31;
    for (int oo = 0; oo < 16; oo++) {
        int o = w * 16 + oo;
        float a0 = bs[o], a1 = bs[o], a2 = bs[o], a3 = bs[o];
        #pragma unroll
        for (int i = 0; i < CIN; i++) {
            float wv = ws[o][i];
            a0 += wv * xs[i][lane];       a1 += wv * xs[i][lane + 32];
            a2 += wv * xs[i][lane + 64];  a3 += wv * xs[i][lane + 96];
        }
        float* dst = h + ((size_t)b * CH + o) * LEN + l0;
        dst[lane] = a0; dst[lane + 32] = a1; dst[lane + 64] = a2; dst[lane + 96] = a3;
    }
}

// ---------------- one WaveNet layer: TL=32, M16xN32 warps, 3 CTAs/SM ----------------
__global__ void __launch_bounds__(THREADS, 3) layer_reg(
    const float* __restrict__ hin, float* __restrict__ hout,
    float* __restrict__ skipout,
    const uint4* __restrict__ w1f, const uint4* __restrict__ w2f,
    const float* __restrict__ csw, const float* __restrict__ cgw,
    const float* __restrict__ z, int off2, int first)
{
    // combined window buffer: [b0h | b0l | b1h | b1l], each [32][BPITCH] bf16.
    // After stage 1, the b1 region is reused as Gx: fp32 g, [128][GXP].
    __shared__ __nv_bfloat16 win[4 * TL * BPITCH];
    __nv_bfloat16* b0h = win;
    __nv_bfloat16* b0l = win + TL * BPITCH;
    __nv_bfloat16* b1h = win + 2 * TL * BPITCH;
    __nv_bfloat16* b1l = win + 3 * TL * BPITCH;
    float* Gx = (float*)(win + 2 * TL * BPITCH);   // 128*GXP*4 = 17408 B = b1 size

    const int t = threadIdx.x, wid = t >> 5, lane = t & 31;
    const int mg = wid;                                    // 8 M-group warps
    const int b = blockIdx.y, l0 = blockIdx.x * TL;

    // ---- fill: batch ALL 32 LDGs first (max MLP), then pack + STS.64 ----
    {
        const int p = lane;
        const int q0 = l0 + p - off2, q1 = l0 + p - 1;
        float v0[16], v1[16];
        const float* base = hin + (size_t)(b * CH + wid * 16) * LEN;
        #pragma unroll
        for (int k = 0; k < 16; k++) {
            const float* row = base + (size_t)k * LEN;
            v0[k] = (q0 >= 0) ? row[q0] : 0.f;
            v1[k] = (q1 >= 0) ? row[q1] : 0.f;
        }
        #pragma unroll
        for (int cc = 0; cc < 4; cc++) {
            const int ch0 = wid * 16 + cc * 4;
            const int k0 = cc * 4;
            uint2 h0v, l0v, h1v, l1v;
            h0v.x = pkbf2(v0[k0 + 0], v0[k0 + 1]);
            h0v.y = pkbf2(v0[k0 + 2], v0[k0 + 3]);
            l0v.x = pkbf2(v0[k0 + 0] - __bfloat162float(__float2bfloat16(v0[k0 + 0])),
                          v0[k0 + 1] - __bfloat162float(__float2bfloat16(v0[k0 + 1])));
            l0v.y = pkbf2(v0[k0 + 2] - __bfloat162float(__float2bfloat16(v0[k0 + 2])),
                          v0[k0 + 3] - __bfloat162float(__float2bfloat16(v0[k0 + 3])));
            h1v.x = pkbf2(v1[k0 + 0], v1[k0 + 1]);
            h1v.y = pkbf2(v1[k0 + 2], v1[k0 + 3]);
            l1v.x = pkbf2(v1[k0 + 0] - __bfloat162float(__float2bfloat16(v1[k0 + 0])),
                          v1[k0 + 1] - __bfloat162float(__float2bfloat16(v1[k0 + 1])));
            l1v.y = pkbf2(v1[k0 + 2] - __bfloat162float(__float2bfloat16(v1[k0 + 2])),
                          v1[k0 + 3] - __bfloat162float(__float2bfloat16(v1[k0 + 3])));
            *(uint2*)&b0h[p * BPITCH + ch0] = h0v;
            *(uint2*)&b0l[p * BPITCH + ch0] = l0v;
            *(uint2*)&b1h[p * BPITCH + ch0] = h1v;
            *(uint2*)&b1l[p * BPITCH + ch0] = l1v;
        }
    }
    __syncthreads();

    float accS[4][4], accG[4][4];
    #pragma unroll
    for (int i = 0; i < 4; i++)
        #pragma unroll
        for (int j = 0; j < 4; j++) { accS[i][j] = 0.f; accG[i][j] = 0.f; }

    const uint32_t b0h_s = sm_u32(b0h), b0l_s = sm_u32(b0l);
    const uint32_t b1h_s = sm_u32(b1h), b1l_s = sm_u32(b1l);
    const int ntx   = (lane >> 4) & 1;
    const int khalf = (lane >> 3) & 1;
    const int brow  = lane & 7;
    const uint32_t r0off = (uint32_t)((ntx * 8 + brow) * (BPITCH * 2)) + (uint32_t)(khalf * 16);
    const uint32_t r1off = r0off + 16u * (BPITCH * 2);

    // ---- stage 1: 16 k-slices (tap x kc x ks), A direct from global ----
    const char* wb1 = (const char*)(w1f + (size_t)mg * 32 + lane);
    #pragma unroll
    for (int s = 0; s < 16; s++) {
        const int tap = s >> 3, kc = (s >> 1) & 3, ks = s & 1;
        uint4 aSh = ldg128(wb1 + (size_t)(s * 4 + 0) * 4096);
        uint4 aSl = ldg128(wb1 + (size_t)(s * 4 + 1) * 4096);
        uint4 aGh = ldg128(wb1 + (size_t)(s * 4 + 2) * 4096);
        uint4 aGl = ldg128(wb1 + (size_t)(s * 4 + 3) * 4096);
        const uint32_t bh_s = tap ? b1h_s : b0h_s;
        const uint32_t bl_s = tap ? b1l_s : b0l_s;
        const uint32_t kb = (uint32_t)((kc * 32 + ks * 16) * 2);
        uint32_t bh0[4], bl0[4], bh1[4], bl1[4];
        ldm_x4(bh0, bh_s + r0off + kb);
        ldm_x4(bl0, bl_s + r0off + kb);
        ldm_x4(bh1, bh_s + r1off + kb);
        ldm_x4(bl1, bl_s + r1off + kb);
        #pragma unroll
        for (int hnt = 0; hnt < 2; hnt++) {
            mma16816(accS[hnt], (const uint32_t*)&aSh, bh0 + 2 * hnt);
            mma16816(accG[hnt], (const uint32_t*)&aGh, bh0 + 2 * hnt);
            mma16816(accS[hnt], (const uint32_t*)&aSh, bl0 + 2 * hnt);
            mma16816(accG[hnt], (const uint32_t*)&aGh, bl0 + 2 * hnt);
            mma16816(accS[hnt], (const uint32_t*)&aSl, bh0 + 2 * hnt);
            mma16816(accG[hnt], (const uint32_t*)&aGl, bh0 + 2 * hnt);
        }
        #pragma unroll
        for (int hnt = 0; hnt < 2; hnt++) {
            mma16816(accS[2 + hnt], (const uint32_t*)&aSh, bh1 + 2 * hnt);
            mma16816(accG[2 + hnt], (const uint32_t*)&aGh, bh1 + 2 * hnt);
            mma16816(accS[2 + hnt], (const uint32_t*)&aSh, bl1 + 2 * hnt);
            mma16816(accG[2 + hnt], (const uint32_t*)&aGh, bl1 + 2 * hnt);
            mma16816(accS[2 + hnt], (const uint32_t*)&aSl, bh1 + 2 * hnt);
            mma16816(accG[2 + hnt], (const uint32_t*)&aGl, bh1 + 2 * hnt);
        }
    }

    // ---- conditioning + gating; g -> window0 (bf16 hi/lo) + Gx (fp32) ----
    const int gid = lane >> 2, tig = lane & 3;
    const int ch0 = mg * 16 + gid;
    {
        float cs0 = csw[ch0], cs1 = csw[ch0 + 8];
        float cg0 = cgw[ch0], cg1 = cgw[ch0 + 8];
        const float* zrow = z + (size_t)b * LEN + l0;
        float gv[4][4];
        #pragma unroll
        for (int nt = 0; nt < 4; nt++) {
            int n0 = nt * 8 + tig * 2;
            float2 zp = *(const float2*)(zrow + n0);
            float s0v = accS[nt][0] + cs0 * zp.x, g0v = accG[nt][0] + cg0 * zp.x;
            float s1v = accS[nt][1] + cs0 * zp.y, g1v = accG[nt][1] + cg0 * zp.y;
            float s2v = accS[nt][2] + cs1 * zp.x, g2v = accG[nt][2] + cg1 * zp.x;
            float s3v = accS[nt][3] + cs1 * zp.y, g3v = accG[nt][3] + cg1 * zp.y;
            gv[nt][0] = s0v / (1.f + __expf(-g0v));
            gv[nt][1] = s1v / (1.f + __expf(-g1v));
            gv[nt][2] = s2v / (1.f + __expf(-g2v));
            gv[nt][3] = s3v / (1.f + __expf(-g3v));
        }
        __syncthreads();   // all stage-1 window reads complete before overwrite
        #pragma unroll
        for (int nt = 0; nt < 4; nt++) {
            int n0 = nt * 8 + tig * 2;
            // bf16 hi/lo for stage-2 B operand
            #pragma unroll
            for (int j = 0; j < 4; j++) {
                int n  = n0 + (j & 1);
                int ch = ch0 + ((j >> 1) << 3);
                __nv_bfloat16 hi = __float2bfloat16(gv[nt][j]);
                b0h[n * BPITCH + ch] = hi;
                b0l[n * BPITCH + ch] = __float2bfloat16(gv[nt][j] - __bfloat162float(hi));
            }
            // fp32 g for the epilogue (Gx[ch][n], float2 per (ch, n-pair))
            *(float2*)&Gx[ch0 * GXP + n0]       = make_float2(gv[nt][0], gv[nt][1]);
            *(float2*)&Gx[(ch0 + 8) * GXP + n0] = make_float2(gv[nt][2], gv[nt][3]);
        }
    }
    #pragma unroll
    for (int i = 0; i < 4; i++)
        #pragma unroll
        for (int j = 0; j < 4; j++) { accS[i][j] = 0.f; accG[i][j] = 0.f; }
    __syncthreads();

    // ---- stage 2: res/skip over g (window0 rows 0..31) ----
    const char* wb2 = (const char*)(w2f + (size_t)mg * 32 + lane);
    #pragma unroll
    for (int s = 0; s < 8; s++) {
        const int kc = s >> 1, ks = s & 1;
        uint4 aRh = ldg128(wb2 + (size_t)(s * 4 + 0) * 4096);
        uint4 aRl = ldg128(wb2 + (size_t)(s * 4 + 1) * 4096);
        uint4 aKh = ldg128(wb2 + (size_t)(s * 4 + 2) * 4096);
        uint4 aKl = ldg128(wb2 + (size_t)(s * 4 + 3) * 4096);
        const uint32_t kb = (uint32_t)((kc * 32 + ks * 16) * 2);
        uint32_t bh0[4], bl0[4], bh1[4], bl1[4];
        ldm_x4(bh0, b0h_s + r0off + kb);
        ldm_x4(bl0, b0l_s + r0off + kb);
        ldm_x4(bh1, b0h_s + r1off + kb);
        ldm_x4(bl1, b0l_s + r1off + kb);
        #pragma unroll
        for (int hnt = 0; hnt < 2; hnt++) {
            mma16816(accS[hnt], (const uint32_t*)&aRh, bh0 + 2 * hnt);
            mma16816(accG[hnt], (const uint32_t*)&aKh, bh0 + 2 * hnt);
            mma16816(accS[hnt], (const uint32_t*)&aRh, bl0 + 2 * hnt);
            mma16816(accG[hnt], (const uint32_t*)&aKh, bl0 + 2 * hnt);
            mma16816(accS[hnt], (const uint32_t*)&aRl, bh0 + 2 * hnt);
            mma16816(accG[hnt], (const uint32_t*)&aKl, bh0 + 2 * hnt);
        }
        #pragma unroll
        for (int hnt = 0; hnt < 2; hnt++) {
            mma16816(accS[2 + hnt], (const uint32_t*)&aRh, bh1 + 2 * hnt);
            mma16816(accG[2 + hnt], (const uint32_t*)&aKh, bh1 + 2 * hnt);
            mma16816(accS[2 + hnt], (const uint32_t*)&aRh, bl1 + 2 * hnt);
            mma16816(accG[2 + hnt], (const uint32_t*)&aKh, bl1 + 2 * hnt);
            mma16816(accS[2 + hnt], (const uint32_t*)&aRl, bh1 + 2 * hnt);
            mma16816(accG[2 + hnt], (const uint32_t*)&aKl, bh1 + 2 * hnt);
        }
    }

    // ---- epilogue: vectorized float2; g from Gx (fp32) ----
    #pragma unroll
    for (int nt = 0; nt < 4; nt++) {
        int n0 = nt * 8 + tig * 2;
        #pragma unroll
        for (int hf = 0; hf < 2; hf++) {
            int ch = ch0 + hf * 8;
            size_t idx = (size_t)(b * CH + ch) * LEN + l0 + n0;
            float r0 = accS[nt][hf * 2 + 0], r1 = accS[nt][hf * 2 + 1];
            float k0 = accG[nt][hf * 2 + 0], k1 = accG[nt][hf * 2 + 1];
            float2 hv;
            if (first) {
                float2 hi2 = *(const float2*)(hin + idx);
                hv.x = hi2.x + r0;
                hv.y = hi2.y + r1;
            } else {
                float2 gp = *(const float2*)&Gx[ch * GXP + n0];
                hv.x = gp.x + r0;
                hv.y = gp.y + r1;
            }
            *(float2*)(hout + idx) = hv;
            if (first) {
                *(float2*)(skipout + idx) = make_float2(k0, k1);
            } else {
                float2 sp = *(const float2*)(skipout + idx);
                sp.x += k0;
                sp.y += k1;
                *(float2*)(skipout + idx) = sp;
            }
        }
    }
}

extern "C" void kernel_launch(void* const* d_in, const int* in_sizes, int n_in,
                              void* d_out, int out_size) {
    (void)in_sizes; (void)n_in; (void)out_size;
    const float* x   = (const float*)d_in[0];
    const float* z   = (const float*)d_in[1];
    const float* w0  = (const float*)d_in[2];
    const float* b0  = (const float*)d_in[3];
    const float* sw  = (const float*)d_in[4];
    const float* gw  = (const float*)d_in[5];
    const float* csw = (const float*)d_in[6];
    const float* cgw = (const float*)d_in[7];
    const float* rw  = (const float*)d_in[8];
    const float* kw  = (const float*)d_in[9];

    float* outH = (float*)d_out;
    float* outS = outH + (size_t)BATCH * CH * LEN;

    float *bufA, *bufB;
    cudaGetSymbolAddress((void**)&bufA, g_bufA);
    cudaGetSymbolAddress((void**)&bufB, g_bufB);
    uint32_t *w1p, *w2p;
    cudaGetSymbolAddress((void**)&w1p, g_w1f);
    cudaGetSymbolAddress((void**)&w2p, g_w2f);

    prep_w1f<<<2048, 256>>>(sw, gw);
    prep_w2f<<<1024, 256>>>(rw, kw);
    proj_kernel<<<dim3(LEN / 128, BATCH), 256>>>(x, w0, b0, bufA);

    const float* cur = bufA;
    for (int ii = 0; ii < NR; ii++) {
        int d    = 1 << ii;
        int off2 = (ii == 0) ? 2 : d + 1;
        float* nxt = (ii == NR - 1) ? outH : ((cur == bufA) ? bufB : bufA);
        layer_reg<<<dim3(LEN / TL, BATCH), THREADS>>>(
            cur, nxt, outS,
            (const uint4*)(w1p + (size_t)ii * 16 * 4 * 8 * 32 * 4),
            (const uint4*)(w2p + (size_t)ii * 8 * 4 * 8 * 32 * 4),
            csw + ii * CH, cgw + ii * CH,
            z, off2, ii == 0 ? 1 : 0);
        cur = nxt;
    }
}